// round 5
// baseline (speedup 1.0000x reference)
#include <cuda_runtime.h>
#include <cstdint>

#define Bb 4
#define Ss 2048
#define Dd 1024
#define Hh 16
#define DHd 64
#define Mm (Bb*Ss)   // 8192

__device__ float g_q[(size_t)Bb*Hh*Ss*DHd];
__device__ float g_k[(size_t)Bb*Hh*Ss*DHd];
__device__ float g_v[(size_t)Bb*Hh*Ss*DHd];
__device__ float g_ctx[(size_t)Mm*Dd];

__device__ __forceinline__ unsigned f2tf(float f) {
    unsigned u; asm("cvt.rna.tf32.f32 %0, %1;" : "=r"(u) : "f"(f)); return u;
}
__device__ __forceinline__ float f2tff(float f) { return __uint_as_float(f2tf(f)); }
__device__ __forceinline__ unsigned su(float f) { return __float_as_uint(f); }

__device__ __forceinline__ void mma_tf32(float* c, unsigned a0, unsigned a1,
                                         unsigned a2, unsigned a3,
                                         unsigned b0, unsigned b1) {
    asm volatile(
        "mma.sync.aligned.m16n8k8.row.col.f32.tf32.tf32.f32 "
        "{%0,%1,%2,%3},{%4,%5,%6,%7},{%8,%9},{%0,%1,%2,%3};"
        : "+f"(c[0]), "+f"(c[1]), "+f"(c[2]), "+f"(c[3])
        : "r"(a0), "r"(a1), "r"(a2), "r"(a3), "r"(b0), "r"(b1));
}

// ============ TF32 GEMM core: C[m,n] = sum_k A[m,k]*W[n,k] ============
// 256 thr (8 warps 2x4), tile 128x128, BK=16, single buffer, two barriers
// (proven R2 structure), stride 20 (conflict-free frag LDS).
#define GST 20

__device__ __forceinline__ void gemm_core(
    const float* __restrict__ A, const float* __restrict__ W,
    float* As, float* Bs, int bm, int bn, float acc[4][4][4])
{
    const int tid = threadIdx.x;
    const int lane = tid & 31, wid = tid >> 5;
    const int wm = wid >> 2, wn = wid & 3;
    const int lr = lane >> 2, lc = lane & 3;

    const int row0 = tid >> 2;            // 0..63
    const int row1 = row0 + 64;           // 64..127
    const int c4 = (tid & 3) * 4;

    float4 pa[2], pb[2];
    pa[0] = *(const float4*)&A[(bm + row0) * Dd + c4];
    pa[1] = *(const float4*)&A[(bm + row1) * Dd + c4];
    pb[0] = *(const float4*)&W[(bn + row0) * Dd + c4];
    pb[1] = *(const float4*)&W[(bn + row1) * Dd + c4];

    for (int k0 = 0; k0 < Dd; k0 += 16) {
        #pragma unroll
        for (int i = 0; i < 2; i++) {
            int row = i ? row1 : row0;
            float4 va = i ? pa[1] : pa[0];
            float4 vb = i ? pb[1] : pb[0];
            *(float4*)&As[row * GST + c4] =
                make_float4(f2tff(va.x), f2tff(va.y), f2tff(va.z), f2tff(va.w));
            *(float4*)&Bs[row * GST + c4] =
                make_float4(f2tff(vb.x), f2tff(vb.y), f2tff(vb.z), f2tff(vb.w));
        }
        __syncthreads();

        if (k0 + 16 < Dd) {
            pa[0] = *(const float4*)&A[(bm + row0) * Dd + k0 + 16 + c4];
            pa[1] = *(const float4*)&A[(bm + row1) * Dd + k0 + 16 + c4];
            pb[0] = *(const float4*)&W[(bn + row0) * Dd + k0 + 16 + c4];
            pb[1] = *(const float4*)&W[(bn + row1) * Dd + k0 + 16 + c4];
        }

        #pragma unroll
        for (int kk = 0; kk < 2; kk++) {
            unsigned af[4][4], bf[4][2];
            const float* Ab = As + (wm * 64 + lr) * GST + kk * 8 + lc;
            #pragma unroll
            for (int mt = 0; mt < 4; mt++) {
                af[mt][0] = su(Ab[mt * 16 * GST]);
                af[mt][1] = su(Ab[mt * 16 * GST + 8 * GST]);
                af[mt][2] = su(Ab[mt * 16 * GST + 4]);
                af[mt][3] = su(Ab[mt * 16 * GST + 8 * GST + 4]);
            }
            const float* Bp = Bs + (wn * 32 + lr) * GST + kk * 8 + lc;
            #pragma unroll
            for (int nt = 0; nt < 4; nt++) {
                bf[nt][0] = su(Bp[nt * 8 * GST]);
                bf[nt][1] = su(Bp[nt * 8 * GST + 4]);
            }
            #pragma unroll
            for (int mt = 0; mt < 4; mt++)
                #pragma unroll
                for (int nt = 0; nt < 4; nt++)
                    mma_tf32(acc[mt][nt], af[mt][0], af[mt][1], af[mt][2], af[mt][3],
                             bf[nt][0], bf[nt][1]);
        }
        __syncthreads();
    }
}

// ============ QKV projection ============
__global__ void __launch_bounds__(256, 2)
qkv_kernel(const float* __restrict__ x,
           const float* __restrict__ Wq, const float* __restrict__ bq,
           const float* __restrict__ Wk, const float* __restrict__ bk,
           const float* __restrict__ Wv, const float* __restrict__ bv)
{
    __shared__ __align__(16) float As[128 * GST];
    __shared__ __align__(16) float Bs[128 * GST];

    const float* W; const float* bias; float* out;
    if (blockIdx.z == 0)      { W = Wq; bias = bq; out = g_q; }
    else if (blockIdx.z == 1) { W = Wk; bias = bk; out = g_k; }
    else                      { W = Wv; bias = bv; out = g_v; }

    const int bm = blockIdx.y * 128, bn = blockIdx.x * 128;
    float acc[4][4][4] = {};
    gemm_core(x, W, As, Bs, bm, bn, acc);

    const int lane = threadIdx.x & 31, wid = threadIdx.x >> 5;
    const int wm = wid >> 2, wn = wid & 3;
    const int lr = lane >> 2, lc = lane & 3;

    #pragma unroll
    for (int mt = 0; mt < 4; mt++) {
        #pragma unroll
        for (int half = 0; half < 2; half++) {
            int m = bm + wm * 64 + mt * 16 + lr + half * 8;
            int b = m >> 11, s = m & 2047;
            #pragma unroll
            for (int nt = 0; nt < 4; nt++) {
                int n = bn + wn * 32 + nt * 8 + 2 * lc;
                int h = n >> 6, d = n & 63;
                float2 v;
                v.x = f2tff(acc[mt][nt][half * 2 + 0] + bias[n]);
                v.y = f2tff(acc[mt][nt][half * 2 + 1] + bias[n + 1]);
                *(float2*)&out[(((b * Hh + h) * Ss + s)) * DHd + d] = v;
            }
        }
    }
}

// ============ Output projection ============
__global__ void __launch_bounds__(256, 2)
oproj_kernel(const float* __restrict__ Wo, const float* __restrict__ bo,
             float* __restrict__ out)
{
    __shared__ __align__(16) float As[128 * GST];
    __shared__ __align__(16) float Bs[128 * GST];

    const int bm = blockIdx.y * 128, bn = blockIdx.x * 128;
    float acc[4][4][4] = {};
    gemm_core(g_ctx, Wo, As, Bs, bm, bn, acc);

    const int lane = threadIdx.x & 31, wid = threadIdx.x >> 5;
    const int wm = wid >> 2, wn = wid & 3;
    const int lr = lane >> 2, lc = lane & 3;

    #pragma unroll
    for (int mt = 0; mt < 4; mt++) {
        #pragma unroll
        for (int half = 0; half < 2; half++) {
            int m = bm + wm * 64 + mt * 16 + lr + half * 8;
            #pragma unroll
            for (int nt = 0; nt < 4; nt++) {
                int n = bn + wn * 32 + nt * 8 + 2 * lc;
                float2 v;
                v.x = acc[mt][nt][half * 2 + 0] + bo[n];
                v.y = acc[mt][nt][half * 2 + 1] + bo[n + 1];
                *(float2*)&out[m * Dd + n] = v;
            }
        }
    }
}

// ============ Flash attention (TF32 MMA) — R2 proven version ============
#define KST 68
#define VST 72
#define PST 68

__global__ void __launch_bounds__(128)
attn_kernel()
{
    __shared__ float Ks[32 * KST];
    __shared__ float Vs[32 * VST];
    __shared__ float Ps[64 * PST];

    const int tid = threadIdx.x;
    const int lane = tid & 31, w = tid >> 5;
    const int lr = lane >> 2, lc = lane & 3;
    const int bh = blockIdx.y;
    const int qb = blockIdx.x * 64;

    const float* Qg = g_q + ((size_t)bh * Ss + qb) * DHd;
    const float* Kg = g_k + (size_t)bh * Ss * DHd;
    const float* Vg = g_v + (size_t)bh * Ss * DHd;

    // Stage Q -> smem -> A-operand frags
    #pragma unroll
    for (int i = 0; i < 8; i++) {
        int f = tid + i * 128, row = f >> 4, c4 = (f & 15) * 4;
        *(float4*)&Ps[row * PST + c4] = *(const float4*)&Qg[row * DHd + c4];
    }
    __syncthreads();
    unsigned qf[8][4];
    #pragma unroll
    for (int ks = 0; ks < 8; ks++) {
        const float* qp = Ps + (w * 16 + lr) * PST + ks * 8 + lc;
        qf[ks][0] = su(qp[0]);
        qf[ks][1] = su(qp[8 * PST]);
        qf[ks][2] = su(qp[4]);
        qf[ks][3] = su(qp[8 * PST + 4]);
    }
    __syncthreads();

    float acc_o[8][4] = {};
    float m0 = -1e30f, m1 = -1e30f, l0 = 0.f, l1 = 0.f;

    float4 pk[4], pv[4];
    #pragma unroll
    for (int i = 0; i < 4; i++) {
        int f = tid + i * 128, row = f >> 4, c4 = (f & 15) * 4;
        pk[i] = *(const float4*)&Kg[row * DHd + c4];
        pv[i] = *(const float4*)&Vg[row * DHd + c4];
    }

    for (int kt = 0; kt < Ss; kt += 32) {
        __syncthreads();
        #pragma unroll
        for (int i = 0; i < 4; i++) {
            int f = tid + i * 128, row = f >> 4, c4 = (f & 15) * 4;
            *(float4*)&Ks[row * KST + c4] = pk[i];
            *(float4*)&Vs[row * VST + c4] = pv[i];
        }
        __syncthreads();

        if (kt + 32 < Ss) {
            #pragma unroll
            for (int i = 0; i < 4; i++) {
                int f = tid + i * 128, row = f >> 4, c4 = (f & 15) * 4;
                pk[i] = *(const float4*)&Kg[(kt + 32 + row) * DHd + c4];
                pv[i] = *(const float4*)&Vg[(kt + 32 + row) * DHd + c4];
            }
        }

        // S = Q K^T
        float s[4][4] = {};
        #pragma unroll
        for (int ks = 0; ks < 8; ks++) {
            #pragma unroll
            for (int nt = 0; nt < 4; nt++) {
                const float* kp = Ks + (nt * 8 + lr) * KST + ks * 8 + lc;
                mma_tf32(s[nt], qf[ks][0], qf[ks][1], qf[ks][2], qf[ks][3],
                         su(kp[0]), su(kp[4]));
            }
        }
        #pragma unroll
        for (int nt = 0; nt < 4; nt++)
            #pragma unroll
            for (int j = 0; j < 4; j++)
                s[nt][j] *= 0.125f;

        // online softmax
        float mx0 = -1e30f, mx1 = -1e30f;
        #pragma unroll
        for (int nt = 0; nt < 4; nt++) {
            mx0 = fmaxf(mx0, fmaxf(s[nt][0], s[nt][1]));
            mx1 = fmaxf(mx1, fmaxf(s[nt][2], s[nt][3]));
        }
        mx0 = fmaxf(mx0, __shfl_xor_sync(0xffffffff, mx0, 1));
        mx0 = fmaxf(mx0, __shfl_xor_sync(0xffffffff, mx0, 2));
        mx1 = fmaxf(mx1, __shfl_xor_sync(0xffffffff, mx1, 1));
        mx1 = fmaxf(mx1, __shfl_xor_sync(0xffffffff, mx1, 2));

        float mn0 = fmaxf(m0, mx0), mn1 = fmaxf(m1, mx1);
        float cr0 = __expf(m0 - mn0), cr1 = __expf(m1 - mn1);
        m0 = mn0; m1 = mn1;

        float ls0 = 0.f, ls1 = 0.f;
        float* pp0 = Ps + (w * 16 + lr) * PST + 2 * lc;
        float* pp1 = pp0 + 8 * PST;
        #pragma unroll
        for (int nt = 0; nt < 4; nt++) {
            float p00 = __expf(s[nt][0] - m0), p01 = __expf(s[nt][1] - m0);
            float p10 = __expf(s[nt][2] - m1), p11 = __expf(s[nt][3] - m1);
            ls0 += p00 + p01; ls1 += p10 + p11;
            *(float2*)&pp0[nt * 8] = make_float2(f2tff(p00), f2tff(p01));
            *(float2*)&pp1[nt * 8] = make_float2(f2tff(p10), f2tff(p11));
        }
        ls0 += __shfl_xor_sync(0xffffffff, ls0, 1);
        ls0 += __shfl_xor_sync(0xffffffff, ls0, 2);
        ls1 += __shfl_xor_sync(0xffffffff, ls1, 1);
        ls1 += __shfl_xor_sync(0xffffffff, ls1, 2);
        l0 = l0 * cr0 + ls0;
        l1 = l1 * cr1 + ls1;

        #pragma unroll
        for (int dt = 0; dt < 8; dt++) {
            acc_o[dt][0] *= cr0; acc_o[dt][1] *= cr0;
            acc_o[dt][2] *= cr1; acc_o[dt][3] *= cr1;
        }
        __syncwarp();

        // O += P V
        #pragma unroll
        for (int ks = 0; ks < 4; ks++) {
            const float* pf = Ps + (w * 16 + lr) * PST + ks * 8 + lc;
            unsigned a0 = su(pf[0]), a1 = su(pf[8 * PST]);
            unsigned a2 = su(pf[4]), a3 = su(pf[8 * PST + 4]);
            #pragma unroll
            for (int dt = 0; dt < 8; dt++) {
                const float* vp = Vs + (ks * 8 + lc) * VST + dt * 8 + lr;
                mma_tf32(acc_o[dt], a0, a1, a2, a3, su(vp[0]), su(vp[4 * VST]));
            }
        }
    }

    const float inv0 = 1.f / l0, inv1 = 1.f / l1;
    const int b = bh >> 4, h = bh & 15;
    const int r0 = b * Ss + qb + w * 16 + lr;
    #pragma unroll
    for (int dt = 0; dt < 8; dt++) {
        int col = h * DHd + dt * 8 + 2 * lc;
        *(float2*)&g_ctx[(size_t)r0 * Dd + col] =
            make_float2(acc_o[dt][0] * inv0, acc_o[dt][1] * inv0);
        *(float2*)&g_ctx[(size_t)(r0 + 8) * Dd + col] =
            make_float2(acc_o[dt][2] * inv1, acc_o[dt][3] * inv1);
    }
}

// ============ launch ============
extern "C" void kernel_launch(void* const* d_in, const int* in_sizes, int n_in,
                              void* d_out, int out_size)
{
    const float* x  = (const float*)d_in[0];
    const float* Wq = (const float*)d_in[1];
    const float* bq = (const float*)d_in[2];
    const float* Wk = (const float*)d_in[3];
    const float* bk = (const float*)d_in[4];
    const float* Wv = (const float*)d_in[5];
    const float* bv = (const float*)d_in[6];
    const float* Wo = (const float*)d_in[7];
    const float* bo = (const float*)d_in[8];
    float* out = (float*)d_out;

    dim3 gQKV(Dd / 128, Mm / 128, 3);
    qkv_kernel<<<gQKV, 256>>>(x, Wq, bq, Wk, bk, Wv, bv);

    dim3 gAtt(Ss / 64, Bb * Hh);
    attn_kernel<<<gAtt, 128>>>();

    dim3 gO(Dd / 128, Mm / 128);
    oproj_kernel<<<gO, 256>>>(Wo, bo, out);
}

// round 8
// speedup vs baseline: 1.2543x; 1.2543x over previous
#include <cuda_runtime.h>
#include <cuda_fp16.h>
#include <cstdint>

#define Bb 4
#define Ss 2048
#define Dd 1024
#define Hh 16
#define DHd 64
#define Mm (Bb*Ss)   // 8192

// Scratch (allocation-free)
__device__ __half g_xh [(size_t)Mm*Dd];
__device__ __half g_wqh[(size_t)Dd*Dd];
__device__ __half g_wkh[(size_t)Dd*Dd];
__device__ __half g_wvh[(size_t)Dd*Dd];
__device__ __half g_woh[(size_t)Dd*Dd];
__device__ float  g_q[(size_t)Bb*Hh*Ss*DHd];
__device__ float  g_k[(size_t)Bb*Hh*Ss*DHd];
__device__ float  g_v[(size_t)Bb*Hh*Ss*DHd];
__device__ __half g_ctxh[(size_t)Mm*Dd];

__device__ __forceinline__ unsigned f2tf(float f) {
    unsigned u; asm("cvt.rna.tf32.f32 %0, %1;" : "=r"(u) : "f"(f)); return u;
}
__device__ __forceinline__ float f2tff(float f) { return __uint_as_float(f2tf(f)); }
__device__ __forceinline__ unsigned su(float f) { return __float_as_uint(f); }
__device__ __forceinline__ unsigned ldu32(const __half* p) {
    return *(const unsigned*)p;
}

__device__ __forceinline__ void mma_tf32(float* c, unsigned a0, unsigned a1,
                                         unsigned a2, unsigned a3,
                                         unsigned b0, unsigned b1) {
    asm volatile(
        "mma.sync.aligned.m16n8k8.row.col.f32.tf32.tf32.f32 "
        "{%0,%1,%2,%3},{%4,%5,%6,%7},{%8,%9},{%0,%1,%2,%3};"
        : "+f"(c[0]), "+f"(c[1]), "+f"(c[2]), "+f"(c[3])
        : "r"(a0), "r"(a1), "r"(a2), "r"(a3), "r"(b0), "r"(b1));
}

__device__ __forceinline__ void mma_f16(float* c, unsigned a0, unsigned a1,
                                        unsigned a2, unsigned a3,
                                        unsigned b0, unsigned b1) {
    asm volatile(
        "mma.sync.aligned.m16n8k16.row.col.f32.f16.f16.f32 "
        "{%0,%1,%2,%3},{%4,%5,%6,%7},{%8,%9},{%0,%1,%2,%3};"
        : "+f"(c[0]), "+f"(c[1]), "+f"(c[2]), "+f"(c[3])
        : "r"(a0), "r"(a1), "r"(a2), "r"(a3), "r"(b0), "r"(b1));
}

// ============ input conversion: fp32 -> fp16 (direct symbol writes) ============
#define X4 (Mm*Dd/4)   // 2M float4
#define W4 (Dd*Dd/4)   // 256K float4

__global__ void cvt_inputs(const float4* __restrict__ x,
                           const float4* __restrict__ wq,
                           const float4* __restrict__ wk,
                           const float4* __restrict__ wv,
                           const float4* __restrict__ wo)
{
    int i = blockIdx.x * blockDim.x + threadIdx.x;
    const float4* src; __half2* dst; int j;
    if (i < X4)              { src = x;  dst = (__half2*)g_xh;  j = i; }
    else if (i < X4 + W4)    { src = wq; dst = (__half2*)g_wqh; j = i - X4; }
    else if (i < X4 + 2*W4)  { src = wk; dst = (__half2*)g_wkh; j = i - X4 - W4; }
    else if (i < X4 + 3*W4)  { src = wv; dst = (__half2*)g_wvh; j = i - X4 - 2*W4; }
    else if (i < X4 + 4*W4)  { src = wo; dst = (__half2*)g_woh; j = i - X4 - 3*W4; }
    else return;
    float4 v = src[j];
    dst[2 * j]     = __floats2half2_rn(v.x, v.y);
    dst[2 * j + 1] = __floats2half2_rn(v.z, v.w);
}

// ============ FP16 GEMM core: C[m,n] = sum_k A[m,k]*W[n,k] ============
// 256 thr (8 warps 2x4), tile 128x128, BK=32, single buffer, two barriers.
#define SH 40

__device__ __forceinline__ void gemm_core_f16(
    const __half* __restrict__ A, const __half* __restrict__ W,
    __half* As, __half* Bs, int bm, int bn, float acc[4][4][4])
{
    const int tid = threadIdx.x;
    const int lane = tid & 31, wid = tid >> 5;
    const int wm = wid >> 2, wn = wid & 3;
    const int lr = lane >> 2, lc = lane & 3;

    const int row = tid >> 1;            // 0..127
    const int cs  = (tid & 1) * 16;      // 0 or 16

    uint4 pa0, pa1, pb0, pb1;
    pa0 = *(const uint4*)&A[(size_t)(bm + row) * Dd + cs];
    pa1 = *(const uint4*)&A[(size_t)(bm + row) * Dd + cs + 8];
    pb0 = *(const uint4*)&W[(size_t)(bn + row) * Dd + cs];
    pb1 = *(const uint4*)&W[(size_t)(bn + row) * Dd + cs + 8];

    for (int k0 = 0; k0 < Dd; k0 += 32) {
        *(uint4*)&As[row * SH + cs]     = pa0;
        *(uint4*)&As[row * SH + cs + 8] = pa1;
        *(uint4*)&Bs[row * SH + cs]     = pb0;
        *(uint4*)&Bs[row * SH + cs + 8] = pb1;
        __syncthreads();

        if (k0 + 32 < Dd) {
            pa0 = *(const uint4*)&A[(size_t)(bm + row) * Dd + k0 + 32 + cs];
            pa1 = *(const uint4*)&A[(size_t)(bm + row) * Dd + k0 + 32 + cs + 8];
            pb0 = *(const uint4*)&W[(size_t)(bn + row) * Dd + k0 + 32 + cs];
            pb1 = *(const uint4*)&W[(size_t)(bn + row) * Dd + k0 + 32 + cs + 8];
        }

        #pragma unroll
        for (int ks = 0; ks < 2; ks++) {
            unsigned af[4][4], bf[4][2];
            #pragma unroll
            for (int mt = 0; mt < 4; mt++) {
                const __half* Ab = As + (wm * 64 + mt * 16 + lr) * SH + ks * 16 + 2 * lc;
                af[mt][0] = ldu32(Ab);
                af[mt][1] = ldu32(Ab + 8 * SH);
                af[mt][2] = ldu32(Ab + 8);
                af[mt][3] = ldu32(Ab + 8 * SH + 8);
            }
            #pragma unroll
            for (int nt = 0; nt < 4; nt++) {
                const __half* Bp = Bs + (wn * 32 + nt * 8 + lr) * SH + ks * 16 + 2 * lc;
                bf[nt][0] = ldu32(Bp);
                bf[nt][1] = ldu32(Bp + 8);
            }
            #pragma unroll
            for (int mt = 0; mt < 4; mt++)
                #pragma unroll
                for (int nt = 0; nt < 4; nt++)
                    mma_f16(acc[mt][nt], af[mt][0], af[mt][1], af[mt][2], af[mt][3],
                            bf[nt][0], bf[nt][1]);
        }
        __syncthreads();
    }
}

// ============ QKV projection (fp16 core, fp32 tf32-rounded outputs) ============
__global__ void __launch_bounds__(256)
qkv_kernel(const float* __restrict__ bq, const float* __restrict__ bk,
           const float* __restrict__ bv)
{
    __shared__ __align__(16) __half As[128 * SH];
    __shared__ __align__(16) __half Bs[128 * SH];

    const __half* W; const float* bias; float* out;
    if (blockIdx.z == 0)      { W = g_wqh; bias = bq; out = g_q; }
    else if (blockIdx.z == 1) { W = g_wkh; bias = bk; out = g_k; }
    else                      { W = g_wvh; bias = bv; out = g_v; }

    const int bm = blockIdx.y * 128, bn = blockIdx.x * 128;
    float acc[4][4][4] = {};
    gemm_core_f16(g_xh, W, As, Bs, bm, bn, acc);

    const int lane = threadIdx.x & 31, wid = threadIdx.x >> 5;
    const int wm = wid >> 2, wn = wid & 3;
    const int lr = lane >> 2, lc = lane & 3;

    #pragma unroll
    for (int mt = 0; mt < 4; mt++) {
        #pragma unroll
        for (int half_ = 0; half_ < 2; half_++) {
            int m = bm + wm * 64 + mt * 16 + lr + half_ * 8;
            int b = m >> 11, s = m & 2047;
            #pragma unroll
            for (int nt = 0; nt < 4; nt++) {
                int n = bn + wn * 32 + nt * 8 + 2 * lc;
                int h = n >> 6, d = n & 63;
                float2 v;
                v.x = f2tff(acc[mt][nt][half_ * 2 + 0] + bias[n]);
                v.y = f2tff(acc[mt][nt][half_ * 2 + 1] + bias[n + 1]);
                *(float2*)&out[(((b * Hh + h) * Ss + s)) * DHd + d] = v;
            }
        }
    }
}

// ============ Output projection (fp16 core) ============
__global__ void __launch_bounds__(256)
oproj_kernel(const float* __restrict__ bo, float* __restrict__ out)
{
    __shared__ __align__(16) __half As[128 * SH];
    __shared__ __align__(16) __half Bs[128 * SH];

    const int bm = blockIdx.y * 128, bn = blockIdx.x * 128;
    float acc[4][4][4] = {};
    gemm_core_f16(g_ctxh, g_woh, As, Bs, bm, bn, acc);

    const int lane = threadIdx.x & 31, wid = threadIdx.x >> 5;
    const int wm = wid >> 2, wn = wid & 3;
    const int lr = lane >> 2, lc = lane & 3;

    #pragma unroll
    for (int mt = 0; mt < 4; mt++) {
        #pragma unroll
        for (int half_ = 0; half_ < 2; half_++) {
            int m = bm + wm * 64 + mt * 16 + lr + half_ * 8;
            #pragma unroll
            for (int nt = 0; nt < 4; nt++) {
                int n = bn + wn * 32 + nt * 8 + 2 * lc;
                float2 v;
                v.x = acc[mt][nt][half_ * 2 + 0] + bo[n];
                v.y = acc[mt][nt][half_ * 2 + 1] + bo[n + 1];
                *(float2*)&out[(size_t)m * Dd + n] = v;
            }
        }
    }
}

// ============ Flash attention (TF32 MMA) — R2/R5 proven version ============
#define KST 68
#define VST 72
#define PST 68

__global__ void __launch_bounds__(128)
attn_kernel()
{
    __shared__ float Ks[32 * KST];
    __shared__ float Vs[32 * VST];
    __shared__ float Ps[64 * PST];

    const int tid = threadIdx.x;
    const int lane = tid & 31, w = tid >> 5;
    const int lr = lane >> 2, lc = lane & 3;
    const int bh = blockIdx.y;
    const int qb = blockIdx.x * 64;

    const float* Qg = g_q + ((size_t)bh * Ss + qb) * DHd;
    const float* Kg = g_k + (size_t)bh * Ss * DHd;
    const float* Vg = g_v + (size_t)bh * Ss * DHd;

    // Stage Q -> smem -> A-operand frags
    #pragma unroll
    for (int i = 0; i < 8; i++) {
        int f = tid + i * 128, row = f >> 4, c4 = (f & 15) * 4;
        *(float4*)&Ps[row * PST + c4] = *(const float4*)&Qg[row * DHd + c4];
    }
    __syncthreads();
    unsigned qf[8][4];
    #pragma unroll
    for (int ks = 0; ks < 8; ks++) {
        const float* qp = Ps + (w * 16 + lr) * PST + ks * 8 + lc;
        qf[ks][0] = su(qp[0]);
        qf[ks][1] = su(qp[8 * PST]);
        qf[ks][2] = su(qp[4]);
        qf[ks][3] = su(qp[8 * PST + 4]);
    }
    __syncthreads();

    float acc_o[8][4] = {};
    float m0 = -1e30f, m1 = -1e30f, l0 = 0.f, l1 = 0.f;

    float4 pk[4], pv[4];
    #pragma unroll
    for (int i = 0; i < 4; i++) {
        int f = tid + i * 128, row = f >> 4, c4 = (f & 15) * 4;
        pk[i] = *(const float4*)&Kg[row * DHd + c4];
        pv[i] = *(const float4*)&Vg[row * DHd + c4];
    }

    for (int kt = 0; kt < Ss; kt += 32) {
        __syncthreads();
        #pragma unroll
        for (int i = 0; i < 4; i++) {
            int f = tid + i * 128, row = f >> 4, c4 = (f & 15) * 4;
            *(float4*)&Ks[row * KST + c4] = pk[i];
            *(float4*)&Vs[row * VST + c4] = pv[i];
        }
        __syncthreads();

        if (kt + 32 < Ss) {
            #pragma unroll
            for (int i = 0; i < 4; i++) {
                int f = tid + i * 128, row = f >> 4, c4 = (f & 15) * 4;
                pk[i] = *(const float4*)&Kg[(kt + 32 + row) * DHd + c4];
                pv[i] = *(const float4*)&Vg[(kt + 32 + row) * DHd + c4];
            }
        }

        // S = Q K^T
        float s[4][4] = {};
        #pragma unroll
        for (int ks = 0; ks < 8; ks++) {
            #pragma unroll
            for (int nt = 0; nt < 4; nt++) {
                const float* kp = Ks + (nt * 8 + lr) * KST + ks * 8 + lc;
                mma_tf32(s[nt], qf[ks][0], qf[ks][1], qf[ks][2], qf[ks][3],
                         su(kp[0]), su(kp[4]));
            }
        }
        #pragma unroll
        for (int nt = 0; nt < 4; nt++)
            #pragma unroll
            for (int j = 0; j < 4; j++)
                s[nt][j] *= 0.125f;

        // online softmax
        float mx0 = -1e30f, mx1 = -1e30f;
        #pragma unroll
        for (int nt = 0; nt < 4; nt++) {
            mx0 = fmaxf(mx0, fmaxf(s[nt][0], s[nt][1]));
            mx1 = fmaxf(mx1, fmaxf(s[nt][2], s[nt][3]));
        }
        mx0 = fmaxf(mx0, __shfl_xor_sync(0xffffffff, mx0, 1));
        mx0 = fmaxf(mx0, __shfl_xor_sync(0xffffffff, mx0, 2));
        mx1 = fmaxf(mx1, __shfl_xor_sync(0xffffffff, mx1, 1));
        mx1 = fmaxf(mx1, __shfl_xor_sync(0xffffffff, mx1, 2));

        float mn0 = fmaxf(m0, mx0), mn1 = fmaxf(m1, mx1);
        float cr0 = __expf(m0 - mn0), cr1 = __expf(m1 - mn1);
        m0 = mn0; m1 = mn1;

        float ls0 = 0.f, ls1 = 0.f;
        float* pp0 = Ps + (w * 16 + lr) * PST + 2 * lc;
        float* pp1 = pp0 + 8 * PST;
        #pragma unroll
        for (int nt = 0; nt < 4; nt++) {
            float p00 = __expf(s[nt][0] - m0), p01 = __expf(s[nt][1] - m0);
            float p10 = __expf(s[nt][2] - m1), p11 = __expf(s[nt][3] - m1);
            ls0 += p00 + p01; ls1 += p10 + p11;
            *(float2*)&pp0[nt * 8] = make_float2(f2tff(p00), f2tff(p01));
            *(float2*)&pp1[nt * 8] = make_float2(f2tff(p10), f2tff(p11));
        }
        ls0 += __shfl_xor_sync(0xffffffff, ls0, 1);
        ls0 += __shfl_xor_sync(0xffffffff, ls0, 2);
        ls1 += __shfl_xor_sync(0xffffffff, ls1, 1);
        ls1 += __shfl_xor_sync(0xffffffff, ls1, 2);
        l0 = l0 * cr0 + ls0;
        l1 = l1 * cr1 + ls1;

        #pragma unroll
        for (int dt = 0; dt < 8; dt++) {
            acc_o[dt][0] *= cr0; acc_o[dt][1] *= cr0;
            acc_o[dt][2] *= cr1; acc_o[dt][3] *= cr1;
        }
        __syncwarp();

        // O += P V
        #pragma unroll
        for (int ks = 0; ks < 4; ks++) {
            const float* pf = Ps + (w * 16 + lr) * PST + ks * 8 + lc;
            unsigned a0 = su(pf[0]), a1 = su(pf[8 * PST]);
            unsigned a2 = su(pf[4]), a3 = su(pf[8 * PST + 4]);
            #pragma unroll
            for (int dt = 0; dt < 8; dt++) {
                const float* vp = Vs + (ks * 8 + lc) * VST + dt * 8 + lr;
                mma_tf32(acc_o[dt], a0, a1, a2, a3, su(vp[0]), su(vp[4 * VST]));
            }
        }
    }

    const float inv0 = 1.f / l0, inv1 = 1.f / l1;
    const int b = bh >> 4, h = bh & 15;
    const int r0 = b * Ss + qb + w * 16 + lr;
    #pragma unroll
    for (int dt = 0; dt < 8; dt++) {
        int col = h * DHd + dt * 8 + 2 * lc;
        *(__half2*)&g_ctxh[(size_t)r0 * Dd + col] =
            __floats2half2_rn(acc_o[dt][0] * inv0, acc_o[dt][1] * inv0);
        *(__half2*)&g_ctxh[(size_t)(r0 + 8) * Dd + col] =
            __floats2half2_rn(acc_o[dt][2] * inv1, acc_o[dt][3] * inv1);
    }
}

// ============ launch ============
extern "C" void kernel_launch(void* const* d_in, const int* in_sizes, int n_in,
                              void* d_out, int out_size)
{
    const float* x  = (const float*)d_in[0];
    const float* Wq = (const float*)d_in[1];
    const float* bq = (const float*)d_in[2];
    const float* Wk = (const float*)d_in[3];
    const float* bk = (const float*)d_in[4];
    const float* Wv = (const float*)d_in[5];
    const float* bv = (const float*)d_in[6];
    const float* Wo = (const float*)d_in[7];
    const float* bo = (const float*)d_in[8];
    float* out = (float*)d_out;

    const int total = X4 + 4 * W4;
    cvt_inputs<<<(total + 255) / 256, 256>>>((const float4*)x, (const float4*)Wq,
                                             (const float4*)Wk, (const float4*)Wv,
                                             (const float4*)Wo);

    dim3 gQKV(Dd / 128, Mm / 128, 3);
    qkv_kernel<<<gQKV, 256>>>(bq, bk, bv);

    dim3 gAtt(Ss / 64, Bb * Hh);
    attn_kernel<<<gAtt, 128>>>();

    dim3 gO(Dd / 128, Mm / 128);
    oproj_kernel<<<gO, 256>>>(bo, out);
}

// round 9
// speedup vs baseline: 1.3449x; 1.0723x over previous
#include <cuda_runtime.h>
#include <cuda_fp16.h>
#include <cstdint>

#define Bb 4
#define Ss 2048
#define Dd 1024
#define Hh 16
#define DHd 64
#define Mm (Bb*Ss)   // 8192

// Scratch (allocation-free)
__device__ __half g_xh [(size_t)Mm*Dd];
__device__ __half g_wqh[(size_t)Dd*Dd];
__device__ __half g_wkh[(size_t)Dd*Dd];
__device__ __half g_wvh[(size_t)Dd*Dd];
__device__ __half g_woh[(size_t)Dd*Dd];
__device__ float  g_q[(size_t)Bb*Hh*Ss*DHd];
__device__ float  g_k[(size_t)Bb*Hh*Ss*DHd];
__device__ float  g_v[(size_t)Bb*Hh*Ss*DHd];
__device__ __half g_ctxh[(size_t)Mm*Dd];

__device__ __forceinline__ unsigned f2tf(float f) {
    unsigned u; asm("cvt.rna.tf32.f32 %0, %1;" : "=r"(u) : "f"(f)); return u;
}
__device__ __forceinline__ float f2tff(float f) { return __uint_as_float(f2tf(f)); }
__device__ __forceinline__ unsigned su(float f) { return __float_as_uint(f); }
__device__ __forceinline__ unsigned ldu32(const __half* p) {
    return *(const unsigned*)p;
}

__device__ __forceinline__ void mma_tf32(float* c, unsigned a0, unsigned a1,
                                         unsigned a2, unsigned a3,
                                         unsigned b0, unsigned b1) {
    asm volatile(
        "mma.sync.aligned.m16n8k8.row.col.f32.tf32.tf32.f32 "
        "{%0,%1,%2,%3},{%4,%5,%6,%7},{%8,%9},{%0,%1,%2,%3};"
        : "+f"(c[0]), "+f"(c[1]), "+f"(c[2]), "+f"(c[3])
        : "r"(a0), "r"(a1), "r"(a2), "r"(a3), "r"(b0), "r"(b1));
}

__device__ __forceinline__ void mma_f16(float* c, unsigned a0, unsigned a1,
                                        unsigned a2, unsigned a3,
                                        unsigned b0, unsigned b1) {
    asm volatile(
        "mma.sync.aligned.m16n8k16.row.col.f32.f16.f16.f32 "
        "{%0,%1,%2,%3},{%4,%5,%6,%7},{%8,%9},{%0,%1,%2,%3};"
        : "+f"(c[0]), "+f"(c[1]), "+f"(c[2]), "+f"(c[3])
        : "r"(a0), "r"(a1), "r"(a2), "r"(a3), "r"(b0), "r"(b1));
}

// ============ input conversion: fp32 -> fp16 (direct symbol writes) ============
#define X4 (Mm*Dd/4)   // 2M float4
#define W4 (Dd*Dd/4)   // 256K float4

__global__ void cvt_inputs(const float4* __restrict__ x,
                           const float4* __restrict__ wq,
                           const float4* __restrict__ wk,
                           const float4* __restrict__ wv,
                           const float4* __restrict__ wo)
{
    int i = blockIdx.x * blockDim.x + threadIdx.x;
    const float4* src; __half2* dst; int j;
    if (i < X4)              { src = x;  dst = (__half2*)g_xh;  j = i; }
    else if (i < X4 + W4)    { src = wq; dst = (__half2*)g_wqh; j = i - X4; }
    else if (i < X4 + 2*W4)  { src = wk; dst = (__half2*)g_wkh; j = i - X4 - W4; }
    else if (i < X4 + 3*W4)  { src = wv; dst = (__half2*)g_wvh; j = i - X4 - 2*W4; }
    else if (i < X4 + 4*W4)  { src = wo; dst = (__half2*)g_woh; j = i - X4 - 3*W4; }
    else return;
    float4 v = src[j];
    dst[2 * j]     = __floats2half2_rn(v.x, v.y);
    dst[2 * j + 1] = __floats2half2_rn(v.z, v.w);
}

// ============ FP16 GEMM core (R8-proven) ============
#define SH 40

__device__ __forceinline__ void gemm_core_f16(
    const __half* __restrict__ A, const __half* __restrict__ W,
    __half* As, __half* Bs, int bm, int bn, float acc[4][4][4])
{
    const int tid = threadIdx.x;
    const int lane = tid & 31, wid = tid >> 5;
    const int wm = wid >> 2, wn = wid & 3;
    const int lr = lane >> 2, lc = lane & 3;

    const int row = tid >> 1;
    const int cs  = (tid & 1) * 16;

    uint4 pa0, pa1, pb0, pb1;
    pa0 = *(const uint4*)&A[(size_t)(bm + row) * Dd + cs];
    pa1 = *(const uint4*)&A[(size_t)(bm + row) * Dd + cs + 8];
    pb0 = *(const uint4*)&W[(size_t)(bn + row) * Dd + cs];
    pb1 = *(const uint4*)&W[(size_t)(bn + row) * Dd + cs + 8];

    for (int k0 = 0; k0 < Dd; k0 += 32) {
        *(uint4*)&As[row * SH + cs]     = pa0;
        *(uint4*)&As[row * SH + cs + 8] = pa1;
        *(uint4*)&Bs[row * SH + cs]     = pb0;
        *(uint4*)&Bs[row * SH + cs + 8] = pb1;
        __syncthreads();

        if (k0 + 32 < Dd) {
            pa0 = *(const uint4*)&A[(size_t)(bm + row) * Dd + k0 + 32 + cs];
            pa1 = *(const uint4*)&A[(size_t)(bm + row) * Dd + k0 + 32 + cs + 8];
            pb0 = *(const uint4*)&W[(size_t)(bn + row) * Dd + k0 + 32 + cs];
            pb1 = *(const uint4*)&W[(size_t)(bn + row) * Dd + k0 + 32 + cs + 8];
        }

        #pragma unroll
        for (int ks = 0; ks < 2; ks++) {
            unsigned af[4][4], bf[4][2];
            #pragma unroll
            for (int mt = 0; mt < 4; mt++) {
                const __half* Ab = As + (wm * 64 + mt * 16 + lr) * SH + ks * 16 + 2 * lc;
                af[mt][0] = ldu32(Ab);
                af[mt][1] = ldu32(Ab + 8 * SH);
                af[mt][2] = ldu32(Ab + 8);
                af[mt][3] = ldu32(Ab + 8 * SH + 8);
            }
            #pragma unroll
            for (int nt = 0; nt < 4; nt++) {
                const __half* Bp = Bs + (wn * 32 + nt * 8 + lr) * SH + ks * 16 + 2 * lc;
                bf[nt][0] = ldu32(Bp);
                bf[nt][1] = ldu32(Bp + 8);
            }
            #pragma unroll
            for (int mt = 0; mt < 4; mt++)
                #pragma unroll
                for (int nt = 0; nt < 4; nt++)
                    mma_f16(acc[mt][nt], af[mt][0], af[mt][1], af[mt][2], af[mt][3],
                            bf[nt][0], bf[nt][1]);
        }
        __syncthreads();
    }
}

// ============ QKV projection (fp16 core, fp32 tf32-rounded outputs) ============
__global__ void __launch_bounds__(256)
qkv_kernel(const float* __restrict__ bq, const float* __restrict__ bk,
           const float* __restrict__ bv)
{
    __shared__ __align__(16) __half As[128 * SH];
    __shared__ __align__(16) __half Bs[128 * SH];

    const __half* W; const float* bias; float* out;
    if (blockIdx.z == 0)      { W = g_wqh; bias = bq; out = g_q; }
    else if (blockIdx.z == 1) { W = g_wkh; bias = bk; out = g_k; }
    else                      { W = g_wvh; bias = bv; out = g_v; }

    const int bm = blockIdx.y * 128, bn = blockIdx.x * 128;
    float acc[4][4][4] = {};
    gemm_core_f16(g_xh, W, As, Bs, bm, bn, acc);

    const int lane = threadIdx.x & 31, wid = threadIdx.x >> 5;
    const int wm = wid >> 2, wn = wid & 3;
    const int lr = lane >> 2, lc = lane & 3;

    #pragma unroll
    for (int mt = 0; mt < 4; mt++) {
        #pragma unroll
        for (int half_ = 0; half_ < 2; half_++) {
            int m = bm + wm * 64 + mt * 16 + lr + half_ * 8;
            int b = m >> 11, s = m & 2047;
            #pragma unroll
            for (int nt = 0; nt < 4; nt++) {
                int n = bn + wn * 32 + nt * 8 + 2 * lc;
                int h = n >> 6, d = n & 63;
                float2 v;
                v.x = f2tff(acc[mt][nt][half_ * 2 + 0] + bias[n]);
                v.y = f2tff(acc[mt][nt][half_ * 2 + 1] + bias[n + 1]);
                *(float2*)&out[(((b * Hh + h) * Ss + s)) * DHd + d] = v;
            }
        }
    }
}

// ============ Output projection (fp16 core) ============
__global__ void __launch_bounds__(256)
oproj_kernel(const float* __restrict__ bo, float* __restrict__ out)
{
    __shared__ __align__(16) __half As[128 * SH];
    __shared__ __align__(16) __half Bs[128 * SH];

    const int bm = blockIdx.y * 128, bn = blockIdx.x * 128;
    float acc[4][4][4] = {};
    gemm_core_f16(g_ctxh, g_woh, As, Bs, bm, bn, acc);

    const int lane = threadIdx.x & 31, wid = threadIdx.x >> 5;
    const int wm = wid >> 2, wn = wid & 3;
    const int lr = lane >> 2, lc = lane & 3;

    #pragma unroll
    for (int mt = 0; mt < 4; mt++) {
        #pragma unroll
        for (int half_ = 0; half_ < 2; half_++) {
            int m = bm + wm * 64 + mt * 16 + lr + half_ * 8;
            #pragma unroll
            for (int nt = 0; nt < 4; nt++) {
                int n = bn + wn * 32 + nt * 8 + 2 * lc;
                float2 v;
                v.x = acc[mt][nt][half_ * 2 + 0] + bo[n];
                v.y = acc[mt][nt][half_ * 2 + 1] + bo[n + 1];
                *(float2*)&out[(size_t)m * Dd + n] = v;
            }
        }
    }
}

// ============ Flash attention (TF32 MMA, 8 warps / 128 q-rows) ============
#define KST 68
#define VST 72
#define PST 36

__global__ void __launch_bounds__(256)
attn_kernel()
{
    __shared__ float Ks[32 * KST];    //  8.7 KB
    __shared__ float Vs[32 * VST];    //  9.2 KB
    __shared__ float Ps[128 * PST];   // 18.4 KB  (P tiles only)

    const int tid = threadIdx.x;
    const int lane = tid & 31, w = tid >> 5;       // 8 warps
    const int lr = lane >> 2, lc = lane & 3;
    const int bh = blockIdx.y;
    const int qb = blockIdx.x * 128;

    const float* Qg = g_q + ((size_t)bh * Ss + qb) * DHd;
    const float* Kg = g_k + (size_t)bh * Ss * DHd;
    const float* Vg = g_v + (size_t)bh * Ss * DHd;

    // Q frags direct from gmem, pre-scaled by 1/sqrt(64)=0.125 (tf32-exact)
    unsigned qf[8][4];
    {
        const float* q0 = Qg + (w * 16 + lr) * DHd;
        #pragma unroll
        for (int ks = 0; ks < 8; ks++) {
            qf[ks][0] = su(0.125f * q0[ks * 8 + lc]);
            qf[ks][1] = su(0.125f * q0[8 * DHd + ks * 8 + lc]);
            qf[ks][2] = su(0.125f * q0[ks * 8 + lc + 4]);
            qf[ks][3] = su(0.125f * q0[8 * DHd + ks * 8 + lc + 4]);
        }
    }

    float acc_o[8][4] = {};
    float m0 = -1e30f, m1 = -1e30f, l0 = 0.f, l1 = 0.f;

    // prefetch K/V tile 0: 32 rows x 16 float4 = 512 float4 each
    float4 pk[2], pv[2];
    #pragma unroll
    for (int i = 0; i < 2; i++) {
        int f = tid + i * 256, row = f >> 4, c4 = (f & 15) * 4;
        pk[i] = *(const float4*)&Kg[row * DHd + c4];
        pv[i] = *(const float4*)&Vg[row * DHd + c4];
    }

    for (int kt = 0; kt < Ss; kt += 32) {
        __syncthreads();
        #pragma unroll
        for (int i = 0; i < 2; i++) {
            int f = tid + i * 256, row = f >> 4, c4 = (f & 15) * 4;
            *(float4*)&Ks[row * KST + c4] = pk[i];
            *(float4*)&Vs[row * VST + c4] = pv[i];
        }
        __syncthreads();

        if (kt + 32 < Ss) {
            #pragma unroll
            for (int i = 0; i < 2; i++) {
                int f = tid + i * 256, row = f >> 4, c4 = (f & 15) * 4;
                pk[i] = *(const float4*)&Kg[(kt + 32 + row) * DHd + c4];
                pv[i] = *(const float4*)&Vg[(kt + 32 + row) * DHd + c4];
            }
        }

        // S = (Q/8) K^T   (16q x 32k per warp)
        float s[4][4] = {};
        #pragma unroll
        for (int ks = 0; ks < 8; ks++) {
            #pragma unroll
            for (int nt = 0; nt < 4; nt++) {
                const float* kp = Ks + (nt * 8 + lr) * KST + ks * 8 + lc;
                mma_tf32(s[nt], qf[ks][0], qf[ks][1], qf[ks][2], qf[ks][3],
                         su(kp[0]), su(kp[4]));
            }
        }

        // online softmax (rows lr, lr+8)
        float mx0 = -1e30f, mx1 = -1e30f;
        #pragma unroll
        for (int nt = 0; nt < 4; nt++) {
            mx0 = fmaxf(mx0, fmaxf(s[nt][0], s[nt][1]));
            mx1 = fmaxf(mx1, fmaxf(s[nt][2], s[nt][3]));
        }
        mx0 = fmaxf(mx0, __shfl_xor_sync(0xffffffff, mx0, 1));
        mx0 = fmaxf(mx0, __shfl_xor_sync(0xffffffff, mx0, 2));
        mx1 = fmaxf(mx1, __shfl_xor_sync(0xffffffff, mx1, 1));
        mx1 = fmaxf(mx1, __shfl_xor_sync(0xffffffff, mx1, 2));

        float mn0 = fmaxf(m0, mx0), mn1 = fmaxf(m1, mx1);
        float cr0 = __expf(m0 - mn0), cr1 = __expf(m1 - mn1);
        m0 = mn0; m1 = mn1;

        float ls0 = 0.f, ls1 = 0.f;
        float* pp0 = Ps + (w * 16 + lr) * PST + 2 * lc;
        float* pp1 = pp0 + 8 * PST;
        #pragma unroll
        for (int nt = 0; nt < 4; nt++) {
            float p00 = __expf(s[nt][0] - m0), p01 = __expf(s[nt][1] - m0);
            float p10 = __expf(s[nt][2] - m1), p11 = __expf(s[nt][3] - m1);
            ls0 += p00 + p01; ls1 += p10 + p11;
            *(float2*)&pp0[nt * 8] = make_float2(f2tff(p00), f2tff(p01));
            *(float2*)&pp1[nt * 8] = make_float2(f2tff(p10), f2tff(p11));
        }
        ls0 += __shfl_xor_sync(0xffffffff, ls0, 1);
        ls0 += __shfl_xor_sync(0xffffffff, ls0, 2);
        ls1 += __shfl_xor_sync(0xffffffff, ls1, 1);
        ls1 += __shfl_xor_sync(0xffffffff, ls1, 2);
        l0 = l0 * cr0 + ls0;
        l1 = l1 * cr1 + ls1;

        #pragma unroll
        for (int dt = 0; dt < 8; dt++) {
            acc_o[dt][0] *= cr0; acc_o[dt][1] *= cr0;
            acc_o[dt][2] *= cr1; acc_o[dt][3] *= cr1;
        }
        __syncwarp();

        // O += P V
        #pragma unroll
        for (int ks = 0; ks < 4; ks++) {
            const float* pf = Ps + (w * 16 + lr) * PST + ks * 8 + lc;
            unsigned a0 = su(pf[0]), a1 = su(pf[8 * PST]);
            unsigned a2 = su(pf[4]), a3 = su(pf[8 * PST + 4]);
            #pragma unroll
            for (int dt = 0; dt < 8; dt++) {
                const float* vp = Vs + (ks * 8 + lc) * VST + dt * 8 + lr;
                mma_tf32(acc_o[dt], a0, a1, a2, a3, su(vp[0]), su(vp[4 * VST]));
            }
        }
    }

    const float inv0 = 1.f / l0, inv1 = 1.f / l1;
    const int b = bh >> 4, h = bh & 15;
    const int r0 = b * Ss + qb + w * 16 + lr;
    #pragma unroll
    for (int dt = 0; dt < 8; dt++) {
        int col = h * DHd + dt * 8 + 2 * lc;
        *(__half2*)&g_ctxh[(size_t)r0 * Dd + col] =
            __floats2half2_rn(acc_o[dt][0] * inv0, acc_o[dt][1] * inv0);
        *(__half2*)&g_ctxh[(size_t)(r0 + 8) * Dd + col] =
            __floats2half2_rn(acc_o[dt][2] * inv1, acc_o[dt][3] * inv1);
    }
}

// ============ launch ============
extern "C" void kernel_launch(void* const* d_in, const int* in_sizes, int n_in,
                              void* d_out, int out_size)
{
    const float* x  = (const float*)d_in[0];
    const float* Wq = (const float*)d_in[1];
    const float* bq = (const float*)d_in[2];
    const float* Wk = (const float*)d_in[3];
    const float* bk = (const float*)d_in[4];
    const float* Wv = (const float*)d_in[5];
    const float* bv = (const float*)d_in[6];
    const float* Wo = (const float*)d_in[7];
    const float* bo = (const float*)d_in[8];
    float* out = (float*)d_out;

    const int total = X4 + 4 * W4;
    cvt_inputs<<<(total + 255) / 256, 256>>>((const float4*)x, (const float4*)Wq,
                                             (const float4*)Wk, (const float4*)Wv,
                                             (const float4*)Wo);

    dim3 gQKV(Dd / 128, Mm / 128, 3);
    qkv_kernel<<<gQKV, 256>>>(bq, bk, bv);

    dim3 gAtt(Ss / 128, Bb * Hh);
    attn_kernel<<<gAtt, 256>>>();

    dim3 gO(Dd / 128, Mm / 128);
    oproj_kernel<<<gO, 256>>>(bo, out);
}

// round 11
// speedup vs baseline: 1.3844x; 1.0293x over previous
#include <cuda_runtime.h>
#include <cuda_fp16.h>
#include <cstdint>

#define Bb 4
#define Ss 2048
#define Dd 1024
#define Hh 16
#define DHd 64
#define Mm (Bb*Ss)   // 8192

// Scratch (allocation-free)
__device__ __half g_xh [(size_t)Mm*Dd];
__device__ __half g_wqh[(size_t)Dd*Dd];
__device__ __half g_wkh[(size_t)Dd*Dd];
__device__ __half g_wvh[(size_t)Dd*Dd];
__device__ __half g_woh[(size_t)Dd*Dd];
__device__ float  g_q[(size_t)Bb*Hh*Ss*DHd];
__device__ float  g_k[(size_t)Bb*Hh*Ss*DHd];
__device__ float  g_v[(size_t)Bb*Hh*Ss*DHd];
__device__ __half g_ctxh[(size_t)Mm*Dd];

__device__ __forceinline__ unsigned f2tf(float f) {
    unsigned u; asm("cvt.rna.tf32.f32 %0, %1;" : "=r"(u) : "f"(f)); return u;
}
__device__ __forceinline__ float f2tff(float f) { return __uint_as_float(f2tf(f)); }
__device__ __forceinline__ unsigned su(float f) { return __float_as_uint(f); }
__device__ __forceinline__ unsigned ldu32(const __half* p) {
    return *(const unsigned*)p;
}

__device__ __forceinline__ void mma_tf32(float* c, unsigned a0, unsigned a1,
                                         unsigned a2, unsigned a3,
                                         unsigned b0, unsigned b1) {
    asm volatile(
        "mma.sync.aligned.m16n8k8.row.col.f32.tf32.tf32.f32 "
        "{%0,%1,%2,%3},{%4,%5,%6,%7},{%8,%9},{%0,%1,%2,%3};"
        : "+f"(c[0]), "+f"(c[1]), "+f"(c[2]), "+f"(c[3])
        : "r"(a0), "r"(a1), "r"(a2), "r"(a3), "r"(b0), "r"(b1));
}

__device__ __forceinline__ void mma_f16(float* c, unsigned a0, unsigned a1,
                                        unsigned a2, unsigned a3,
                                        unsigned b0, unsigned b1) {
    asm volatile(
        "mma.sync.aligned.m16n8k16.row.col.f32.f16.f16.f32 "
        "{%0,%1,%2,%3},{%4,%5,%6,%7},{%8,%9},{%0,%1,%2,%3};"
        : "+f"(c[0]), "+f"(c[1]), "+f"(c[2]), "+f"(c[3])
        : "r"(a0), "r"(a1), "r"(a2), "r"(a3), "r"(b0), "r"(b1));
}

// ============ input conversion: fp32 -> fp16 (direct symbol writes) ============
#define X4 (Mm*Dd/4)
#define W4 (Dd*Dd/4)

__global__ void cvt_inputs(const float4* __restrict__ x,
                           const float4* __restrict__ wq,
                           const float4* __restrict__ wk,
                           const float4* __restrict__ wv,
                           const float4* __restrict__ wo)
{
    int i = blockIdx.x * blockDim.x + threadIdx.x;
    const float4* src; __half2* dst; int j;
    if (i < X4)              { src = x;  dst = (__half2*)g_xh;  j = i; }
    else if (i < X4 + W4)    { src = wq; dst = (__half2*)g_wqh; j = i - X4; }
    else if (i < X4 + 2*W4)  { src = wk; dst = (__half2*)g_wkh; j = i - X4 - W4; }
    else if (i < X4 + 3*W4)  { src = wv; dst = (__half2*)g_wvh; j = i - X4 - 2*W4; }
    else if (i < X4 + 4*W4)  { src = wo; dst = (__half2*)g_woh; j = i - X4 - 3*W4; }
    else return;
    float4 v = src[j];
    dst[2 * j]     = __floats2half2_rn(v.x, v.y);
    dst[2 * j + 1] = __floats2half2_rn(v.z, v.w);
}

// ============ FP16 GEMM core (double-buffered smem, ONE barrier per K-step) ====
// Row length = 32 halves, stride SH=40 >= 32. (Stride bug class checked.)
#define SH 40
#define BUFH (128 * SH)

__device__ __forceinline__ void gemm_core_f16(
    const __half* __restrict__ A, const __half* __restrict__ W,
    __half* As, __half* Bs, int bm, int bn, float acc[4][4][4])
{
    const int tid = threadIdx.x;
    const int lane = tid & 31, wid = tid >> 5;
    const int wm = wid >> 2, wn = wid & 3;
    const int lr = lane >> 2, lc = lane & 3;

    const int row = tid >> 1;
    const int cs  = (tid & 1) * 16;

    uint4 pa0, pa1, pb0, pb1;
    pa0 = *(const uint4*)&A[(size_t)(bm + row) * Dd + cs];
    pa1 = *(const uint4*)&A[(size_t)(bm + row) * Dd + cs + 8];
    pb0 = *(const uint4*)&W[(size_t)(bn + row) * Dd + cs];
    pb1 = *(const uint4*)&W[(size_t)(bn + row) * Dd + cs + 8];

    for (int k0 = 0; k0 < Dd; k0 += 32) {
        const int buf = (k0 >> 5) & 1;
        __half* as = As + buf * BUFH;
        __half* bs = Bs + buf * BUFH;

        *(uint4*)&as[row * SH + cs]     = pa0;
        *(uint4*)&as[row * SH + cs + 8] = pa1;
        *(uint4*)&bs[row * SH + cs]     = pb0;
        *(uint4*)&bs[row * SH + cs + 8] = pb1;
        __syncthreads();   // single barrier: fences iter i-1 reads vs iter i+1 writes

        if (k0 + 32 < Dd) {
            pa0 = *(const uint4*)&A[(size_t)(bm + row) * Dd + k0 + 32 + cs];
            pa1 = *(const uint4*)&A[(size_t)(bm + row) * Dd + k0 + 32 + cs + 8];
            pb0 = *(const uint4*)&W[(size_t)(bn + row) * Dd + k0 + 32 + cs];
            pb1 = *(const uint4*)&W[(size_t)(bn + row) * Dd + k0 + 32 + cs + 8];
        }

        #pragma unroll
        for (int ks = 0; ks < 2; ks++) {
            unsigned af[4][4], bf[4][2];
            #pragma unroll
            for (int mt = 0; mt < 4; mt++) {
                const __half* Ab = as + (wm * 64 + mt * 16 + lr) * SH + ks * 16 + 2 * lc;
                af[mt][0] = ldu32(Ab);
                af[mt][1] = ldu32(Ab + 8 * SH);
                af[mt][2] = ldu32(Ab + 8);
                af[mt][3] = ldu32(Ab + 8 * SH + 8);
            }
            #pragma unroll
            for (int nt = 0; nt < 4; nt++) {
                const __half* Bp = bs + (wn * 32 + nt * 8 + lr) * SH + ks * 16 + 2 * lc;
                bf[nt][0] = ldu32(Bp);
                bf[nt][1] = ldu32(Bp + 8);
            }
            #pragma unroll
            for (int mt = 0; mt < 4; mt++)
                #pragma unroll
                for (int nt = 0; nt < 4; nt++)
                    mma_f16(acc[mt][nt], af[mt][0], af[mt][1], af[mt][2], af[mt][3],
                            bf[nt][0], bf[nt][1]);
        }
        // no trailing barrier (double-buffered)
    }
}

// ============ QKV projection ============
__global__ void __launch_bounds__(256)
qkv_kernel(const float* __restrict__ bq, const float* __restrict__ bk,
           const float* __restrict__ bv)
{
    __shared__ __align__(16) __half As[2 * BUFH];
    __shared__ __align__(16) __half Bs[2 * BUFH];

    const __half* W; const float* bias; float* out;
    if (blockIdx.z == 0)      { W = g_wqh; bias = bq; out = g_q; }
    else if (blockIdx.z == 1) { W = g_wkh; bias = bk; out = g_k; }
    else                      { W = g_wvh; bias = bv; out = g_v; }

    const int bm = blockIdx.y * 128, bn = blockIdx.x * 128;
    float acc[4][4][4] = {};
    gemm_core_f16(g_xh, W, As, Bs, bm, bn, acc);

    const int lane = threadIdx.x & 31, wid = threadIdx.x >> 5;
    const int wm = wid >> 2, wn = wid & 3;
    const int lr = lane >> 2, lc = lane & 3;

    #pragma unroll
    for (int mt = 0; mt < 4; mt++) {
        #pragma unroll
        for (int half_ = 0; half_ < 2; half_++) {
            int m = bm + wm * 64 + mt * 16 + lr + half_ * 8;
            int b = m >> 11, s = m & 2047;
            #pragma unroll
            for (int nt = 0; nt < 4; nt++) {
                int n = bn + wn * 32 + nt * 8 + 2 * lc;
                int h = n >> 6, d = n & 63;
                float2 v;
                v.x = f2tff(acc[mt][nt][half_ * 2 + 0] + bias[n]);
                v.y = f2tff(acc[mt][nt][half_ * 2 + 1] + bias[n + 1]);
                *(float2*)&out[(((b * Hh + h) * Ss + s)) * DHd + d] = v;
            }
        }
    }
}

// ============ Output projection ============
__global__ void __launch_bounds__(256)
oproj_kernel(const float* __restrict__ bo, float* __restrict__ out)
{
    __shared__ __align__(16) __half As[2 * BUFH];
    __shared__ __align__(16) __half Bs[2 * BUFH];

    const int bm = blockIdx.y * 128, bn = blockIdx.x * 128;
    float acc[4][4][4] = {};
    gemm_core_f16(g_ctxh, g_woh, As, Bs, bm, bn, acc);

    const int lane = threadIdx.x & 31, wid = threadIdx.x >> 5;
    const int wm = wid >> 2, wn = wid & 3;
    const int lr = lane >> 2, lc = lane & 3;

    #pragma unroll
    for (int mt = 0; mt < 4; mt++) {
        #pragma unroll
        for (int half_ = 0; half_ < 2; half_++) {
            int m = bm + wm * 64 + mt * 16 + lr + half_ * 8;
            #pragma unroll
            for (int nt = 0; nt < 4; nt++) {
                int n = bn + wn * 32 + nt * 8 + 2 * lc;
                float2 v;
                v.x = acc[mt][nt][half_ * 2 + 0] + bo[n];
                v.y = acc[mt][nt][half_ * 2 + 1] + bo[n + 1];
                *(float2*)&out[(size_t)m * Dd + n] = v;
            }
        }
    }
}

// ============ Flash attention (TF32 MMA, 8 warps, DB K/V, one barrier) ============
// K/V tile row = 64 floats -> strides MUST be >= 64. KST=68, VST=72 (R2/R9-proven
// conflict classes). P tile row = 32 floats, PST=36.
#define KST 68
#define VST 72
#define PST 36
#define KBUF (32 * KST)
#define VBUF (32 * VST)
#define ATT_SMEM ((2 * KBUF + 2 * VBUF + 128 * PST) * 4)   // 54272 B

__global__ void __launch_bounds__(256)
attn_kernel()
{
    extern __shared__ __align__(16) float dsm[];
    float* Ks = dsm;                       // [2][32*KST]
    float* Vs = dsm + 2 * KBUF;            // [2][32*VST]
    float* Ps = dsm + 2 * KBUF + 2 * VBUF; // [128*PST]

    const int tid = threadIdx.x;
    const int lane = tid & 31, w = tid >> 5;
    const int lr = lane >> 2, lc = lane & 3;
    const int bh = blockIdx.y;
    const int qb = blockIdx.x * 128;

    const float* Qg = g_q + ((size_t)bh * Ss + qb) * DHd;
    const float* Kg = g_k + (size_t)bh * Ss * DHd;
    const float* Vg = g_v + (size_t)bh * Ss * DHd;

    // Q frags direct from gmem, pre-scaled by 0.125 (tf32-exact)
    unsigned qf[8][4];
    {
        const float* q0 = Qg + (w * 16 + lr) * DHd;
        #pragma unroll
        for (int ks = 0; ks < 8; ks++) {
            qf[ks][0] = su(0.125f * q0[ks * 8 + lc]);
            qf[ks][1] = su(0.125f * q0[8 * DHd + ks * 8 + lc]);
            qf[ks][2] = su(0.125f * q0[ks * 8 + lc + 4]);
            qf[ks][3] = su(0.125f * q0[8 * DHd + ks * 8 + lc + 4]);
        }
    }

    float acc_o[8][4] = {};
    float m0 = -1e30f, m1 = -1e30f, l0 = 0.f, l1 = 0.f;

    float4 pk[2], pv[2];
    #pragma unroll
    for (int i = 0; i < 2; i++) {
        int f = tid + i * 256, row = f >> 4, c4 = (f & 15) * 4;
        pk[i] = *(const float4*)&Kg[row * DHd + c4];
        pv[i] = *(const float4*)&Vg[row * DHd + c4];
    }

    for (int kt = 0; kt < Ss; kt += 32) {
        const int buf = (kt >> 5) & 1;
        float* ksm = Ks + buf * KBUF;
        float* vsm = Vs + buf * VBUF;

        #pragma unroll
        for (int i = 0; i < 2; i++) {
            int f = tid + i * 256, row = f >> 4, c4 = (f & 15) * 4;
            *(float4*)&ksm[row * KST + c4] = pk[i];
            *(float4*)&vsm[row * VST + c4] = pv[i];
        }
        __syncthreads();   // single barrier (double-buffered)

        if (kt + 32 < Ss) {
            #pragma unroll
            for (int i = 0; i < 2; i++) {
                int f = tid + i * 256, row = f >> 4, c4 = (f & 15) * 4;
                pk[i] = *(const float4*)&Kg[(kt + 32 + row) * DHd + c4];
                pv[i] = *(const float4*)&Vg[(kt + 32 + row) * DHd + c4];
            }
        }

        // S = (Q/8) K^T
        float s[4][4] = {};
        #pragma unroll
        for (int ks = 0; ks < 8; ks++) {
            #pragma unroll
            for (int nt = 0; nt < 4; nt++) {
                const float* kp = ksm + (nt * 8 + lr) * KST + ks * 8 + lc;
                mma_tf32(s[nt], qf[ks][0], qf[ks][1], qf[ks][2], qf[ks][3],
                         su(kp[0]), su(kp[4]));
            }
        }

        // online softmax
        float mx0 = -1e30f, mx1 = -1e30f;
        #pragma unroll
        for (int nt = 0; nt < 4; nt++) {
            mx0 = fmaxf(mx0, fmaxf(s[nt][0], s[nt][1]));
            mx1 = fmaxf(mx1, fmaxf(s[nt][2], s[nt][3]));
        }
        mx0 = fmaxf(mx0, __shfl_xor_sync(0xffffffff, mx0, 1));
        mx0 = fmaxf(mx0, __shfl_xor_sync(0xffffffff, mx0, 2));
        mx1 = fmaxf(mx1, __shfl_xor_sync(0xffffffff, mx1, 1));
        mx1 = fmaxf(mx1, __shfl_xor_sync(0xffffffff, mx1, 2));

        float mn0 = fmaxf(m0, mx0), mn1 = fmaxf(m1, mx1);
        float cr0 = __expf(m0 - mn0), cr1 = __expf(m1 - mn1);
        m0 = mn0; m1 = mn1;

        float ls0 = 0.f, ls1 = 0.f;
        float* pp0 = Ps + (w * 16 + lr) * PST + 2 * lc;
        float* pp1 = pp0 + 8 * PST;
        #pragma unroll
        for (int nt = 0; nt < 4; nt++) {
            float p00 = __expf(s[nt][0] - m0), p01 = __expf(s[nt][1] - m0);
            float p10 = __expf(s[nt][2] - m1), p11 = __expf(s[nt][3] - m1);
            ls0 += p00 + p01; ls1 += p10 + p11;
            *(float2*)&pp0[nt * 8] = make_float2(f2tff(p00), f2tff(p01));
            *(float2*)&pp1[nt * 8] = make_float2(f2tff(p10), f2tff(p11));
        }
        ls0 += __shfl_xor_sync(0xffffffff, ls0, 1);
        ls0 += __shfl_xor_sync(0xffffffff, ls0, 2);
        ls1 += __shfl_xor_sync(0xffffffff, ls1, 1);
        ls1 += __shfl_xor_sync(0xffffffff, ls1, 2);
        l0 = l0 * cr0 + ls0;
        l1 = l1 * cr1 + ls1;

        #pragma unroll
        for (int dt = 0; dt < 8; dt++) {
            acc_o[dt][0] *= cr0; acc_o[dt][1] *= cr0;
            acc_o[dt][2] *= cr1; acc_o[dt][3] *= cr1;
        }
        __syncwarp();

        // O += P V
        #pragma unroll
        for (int ks = 0; ks < 4; ks++) {
            const float* pf = Ps + (w * 16 + lr) * PST + ks * 8 + lc;
            unsigned a0 = su(pf[0]), a1 = su(pf[8 * PST]);
            unsigned a2 = su(pf[4]), a3 = su(pf[8 * PST + 4]);
            #pragma unroll
            for (int dt = 0; dt < 8; dt++) {
                const float* vp = vsm + (ks * 8 + lc) * VST + dt * 8 + lr;
                mma_tf32(acc_o[dt], a0, a1, a2, a3, su(vp[0]), su(vp[4 * VST]));
            }
        }
        // no trailing barrier (double-buffered)
    }

    const float inv0 = 1.f / l0, inv1 = 1.f / l1;
    const int b = bh >> 4, h = bh & 15;
    const int r0 = b * Ss + qb + w * 16 + lr;
    #pragma unroll
    for (int dt = 0; dt < 8; dt++) {
        int col = h * DHd + dt * 8 + 2 * lc;
        *(__half2*)&g_ctxh[(size_t)r0 * Dd + col] =
            __floats2half2_rn(acc_o[dt][0] * inv0, acc_o[dt][1] * inv0);
        *(__half2*)&g_ctxh[(size_t)(r0 + 8) * Dd + col] =
            __floats2half2_rn(acc_o[dt][2] * inv1, acc_o[dt][3] * inv1);
    }
}

// ============ launch ============
extern "C" void kernel_launch(void* const* d_in, const int* in_sizes, int n_in,
                              void* d_out, int out_size)
{
    const float* x  = (const float*)d_in[0];
    const float* Wq = (const float*)d_in[1];
    const float* bq = (const float*)d_in[2];
    const float* Wk = (const float*)d_in[3];
    const float* bk = (const float*)d_in[4];
    const float* Wv = (const float*)d_in[5];
    const float* bv = (const float*)d_in[6];
    const float* Wo = (const float*)d_in[7];
    const float* bo = (const float*)d_in[8];
    float* out = (float*)d_out;

    cudaFuncSetAttribute(attn_kernel, cudaFuncAttributeMaxDynamicSharedMemorySize,
                         ATT_SMEM);

    const int total = X4 + 4 * W4;
    cvt_inputs<<<(total + 255) / 256, 256>>>((const float4*)x, (const float4*)Wq,
                                             (const float4*)Wk, (const float4*)Wv,
                                             (const float4*)Wo);

    dim3 gQKV(Dd / 128, Mm / 128, 3);
    qkv_kernel<<<gQKV, 256>>>(bq, bk, bv);

    dim3 gAtt(Ss / 128, Bb * Hh);
    attn_kernel<<<gAtt, 256, ATT_SMEM>>>();

    dim3 gO(Dd / 128, Mm / 128);
    oproj_kernel<<<gO, 256>>>(bo, out);
}

// round 12
// speedup vs baseline: 1.5194x; 1.0975x over previous
#include <cuda_runtime.h>
#include <cuda_fp16.h>
#include <cstdint>

#define Bb 4
#define Ss 2048
#define Dd 1024
#define Hh 16
#define DHd 64
#define Mm (Bb*Ss)   // 8192

// Scratch (allocation-free)
__device__ __half g_xh [(size_t)Mm*Dd];
__device__ __half g_wqh[(size_t)Dd*Dd];
__device__ __half g_wkh[(size_t)Dd*Dd];
__device__ __half g_wvh[(size_t)Dd*Dd];
__device__ __half g_woh[(size_t)Dd*Dd];
__device__ __half g_qh [(size_t)Bb*Hh*Ss*DHd];   // q, pre-scaled by 0.125, fp16
__device__ __half g_kh [(size_t)Bb*Hh*Ss*DHd];   // k, fp16
__device__ float  g_v  [(size_t)Bb*Hh*Ss*DHd];   // v, fp32 (tf32-rounded)
__device__ __half g_ctxh[(size_t)Mm*Dd];

__device__ __forceinline__ unsigned f2tf(float f) {
    unsigned u; asm("cvt.rna.tf32.f32 %0, %1;" : "=r"(u) : "f"(f)); return u;
}
__device__ __forceinline__ float f2tff(float f) { return __uint_as_float(f2tf(f)); }
__device__ __forceinline__ unsigned su(float f) { return __float_as_uint(f); }
__device__ __forceinline__ unsigned ldu32(const __half* p) {
    return *(const unsigned*)p;
}

__device__ __forceinline__ void mma_tf32(float* c, unsigned a0, unsigned a1,
                                         unsigned a2, unsigned a3,
                                         unsigned b0, unsigned b1) {
    asm volatile(
        "mma.sync.aligned.m16n8k8.row.col.f32.tf32.tf32.f32 "
        "{%0,%1,%2,%3},{%4,%5,%6,%7},{%8,%9},{%0,%1,%2,%3};"
        : "+f"(c[0]), "+f"(c[1]), "+f"(c[2]), "+f"(c[3])
        : "r"(a0), "r"(a1), "r"(a2), "r"(a3), "r"(b0), "r"(b1));
}

__device__ __forceinline__ void mma_f16(float* c, unsigned a0, unsigned a1,
                                        unsigned a2, unsigned a3,
                                        unsigned b0, unsigned b1) {
    asm volatile(
        "mma.sync.aligned.m16n8k16.row.col.f32.f16.f16.f32 "
        "{%0,%1,%2,%3},{%4,%5,%6,%7},{%8,%9},{%0,%1,%2,%3};"
        : "+f"(c[0]), "+f"(c[1]), "+f"(c[2]), "+f"(c[3])
        : "r"(a0), "r"(a1), "r"(a2), "r"(a3), "r"(b0), "r"(b1));
}

// ============ input conversion: fp32 -> fp16 (direct symbol writes) ============
#define X4 (Mm*Dd/4)
#define W4 (Dd*Dd/4)

__global__ void cvt_inputs(const float4* __restrict__ x,
                           const float4* __restrict__ wq,
                           const float4* __restrict__ wk,
                           const float4* __restrict__ wv,
                           const float4* __restrict__ wo)
{
    int i = blockIdx.x * blockDim.x + threadIdx.x;
    const float4* src; __half2* dst; int j;
    if (i < X4)              { src = x;  dst = (__half2*)g_xh;  j = i; }
    else if (i < X4 + W4)    { src = wq; dst = (__half2*)g_wqh; j = i - X4; }
    else if (i < X4 + 2*W4)  { src = wk; dst = (__half2*)g_wkh; j = i - X4 - W4; }
    else if (i < X4 + 3*W4)  { src = wv; dst = (__half2*)g_wvh; j = i - X4 - 2*W4; }
    else if (i < X4 + 4*W4)  { src = wo; dst = (__half2*)g_woh; j = i - X4 - 3*W4; }
    else return;
    float4 v = src[j];
    dst[2 * j]     = __floats2half2_rn(v.x, v.y);
    dst[2 * j + 1] = __floats2half2_rn(v.z, v.w);
}

// ============ FP16 GEMM core (R11-proven: DB smem, one barrier/K-step) ============
#define SH 40
#define BUFH (128 * SH)

__device__ __forceinline__ void gemm_core_f16(
    const __half* __restrict__ A, const __half* __restrict__ W,
    __half* As, __half* Bs, int bm, int bn, float acc[4][4][4])
{
    const int tid = threadIdx.x;
    const int lane = tid & 31, wid = tid >> 5;
    const int wm = wid >> 2, wn = wid & 3;
    const int lr = lane >> 2, lc = lane & 3;

    const int row = tid >> 1;
    const int cs  = (tid & 1) * 16;

    uint4 pa0, pa1, pb0, pb1;
    pa0 = *(const uint4*)&A[(size_t)(bm + row) * Dd + cs];
    pa1 = *(const uint4*)&A[(size_t)(bm + row) * Dd + cs + 8];
    pb0 = *(const uint4*)&W[(size_t)(bn + row) * Dd + cs];
    pb1 = *(const uint4*)&W[(size_t)(bn + row) * Dd + cs + 8];

    for (int k0 = 0; k0 < Dd; k0 += 32) {
        const int buf = (k0 >> 5) & 1;
        __half* as = As + buf * BUFH;
        __half* bs = Bs + buf * BUFH;

        *(uint4*)&as[row * SH + cs]     = pa0;
        *(uint4*)&as[row * SH + cs + 8] = pa1;
        *(uint4*)&bs[row * SH + cs]     = pb0;
        *(uint4*)&bs[row * SH + cs + 8] = pb1;
        __syncthreads();

        if (k0 + 32 < Dd) {
            pa0 = *(const uint4*)&A[(size_t)(bm + row) * Dd + k0 + 32 + cs];
            pa1 = *(const uint4*)&A[(size_t)(bm + row) * Dd + k0 + 32 + cs + 8];
            pb0 = *(const uint4*)&W[(size_t)(bn + row) * Dd + k0 + 32 + cs];
            pb1 = *(const uint4*)&W[(size_t)(bn + row) * Dd + k0 + 32 + cs + 8];
        }

        #pragma unroll
        for (int ks = 0; ks < 2; ks++) {
            unsigned af[4][4], bf[4][2];
            #pragma unroll
            for (int mt = 0; mt < 4; mt++) {
                const __half* Ab = as + (wm * 64 + mt * 16 + lr) * SH + ks * 16 + 2 * lc;
                af[mt][0] = ldu32(Ab);
                af[mt][1] = ldu32(Ab + 8 * SH);
                af[mt][2] = ldu32(Ab + 8);
                af[mt][3] = ldu32(Ab + 8 * SH + 8);
            }
            #pragma unroll
            for (int nt = 0; nt < 4; nt++) {
                const __half* Bp = bs + (wn * 32 + nt * 8 + lr) * SH + ks * 16 + 2 * lc;
                bf[nt][0] = ldu32(Bp);
                bf[nt][1] = ldu32(Bp + 8);
            }
            #pragma unroll
            for (int mt = 0; mt < 4; mt++)
                #pragma unroll
                for (int nt = 0; nt < 4; nt++)
                    mma_f16(acc[mt][nt], af[mt][0], af[mt][1], af[mt][2], af[mt][3],
                            bf[nt][0], bf[nt][1]);
        }
    }
}

// ============ QKV projection (q,k -> fp16; v -> fp32 tf32-rounded) ============
__global__ void __launch_bounds__(256)
qkv_kernel(const float* __restrict__ bq, const float* __restrict__ bk,
           const float* __restrict__ bv)
{
    __shared__ __align__(16) __half As[2 * BUFH];
    __shared__ __align__(16) __half Bs[2 * BUFH];

    const __half* W; const float* bias; const int which = blockIdx.z;
    if (which == 0)      { W = g_wqh; bias = bq; }
    else if (which == 1) { W = g_wkh; bias = bk; }
    else                 { W = g_wvh; bias = bv; }

    const int bm = blockIdx.y * 128, bn = blockIdx.x * 128;
    float acc[4][4][4] = {};
    gemm_core_f16(g_xh, W, As, Bs, bm, bn, acc);

    const int lane = threadIdx.x & 31, wid = threadIdx.x >> 5;
    const int wm = wid >> 2, wn = wid & 3;
    const int lr = lane >> 2, lc = lane & 3;

    #pragma unroll
    for (int mt = 0; mt < 4; mt++) {
        #pragma unroll
        for (int half_ = 0; half_ < 2; half_++) {
            int m = bm + wm * 64 + mt * 16 + lr + half_ * 8;
            int b = m >> 11, s = m & 2047;
            #pragma unroll
            for (int nt = 0; nt < 4; nt++) {
                int n = bn + wn * 32 + nt * 8 + 2 * lc;
                int h = n >> 6, d = n & 63;
                float vx = acc[mt][nt][half_ * 2 + 0] + bias[n];
                float vy = acc[mt][nt][half_ * 2 + 1] + bias[n + 1];
                size_t idx = ((size_t)((b * Hh + h) * Ss + s)) * DHd + d;
                if (which == 0) {
                    *(__half2*)&g_qh[idx] = __floats2half2_rn(0.125f * vx, 0.125f * vy);
                } else if (which == 1) {
                    *(__half2*)&g_kh[idx] = __floats2half2_rn(vx, vy);
                } else {
                    *(float2*)&g_v[idx] = make_float2(f2tff(vx), f2tff(vy));
                }
            }
        }
    }
}

// ============ Output projection (R11-proven) ============
__global__ void __launch_bounds__(256)
oproj_kernel(const float* __restrict__ bo, float* __restrict__ out)
{
    __shared__ __align__(16) __half As[2 * BUFH];
    __shared__ __align__(16) __half Bs[2 * BUFH];

    const int bm = blockIdx.y * 128, bn = blockIdx.x * 128;
    float acc[4][4][4] = {};
    gemm_core_f16(g_ctxh, g_woh, As, Bs, bm, bn, acc);

    const int lane = threadIdx.x & 31, wid = threadIdx.x >> 5;
    const int wm = wid >> 2, wn = wid & 3;
    const int lr = lane >> 2, lc = lane & 3;

    #pragma unroll
    for (int mt = 0; mt < 4; mt++) {
        #pragma unroll
        for (int half_ = 0; half_ < 2; half_++) {
            int m = bm + wm * 64 + mt * 16 + lr + half_ * 8;
            #pragma unroll
            for (int nt = 0; nt < 4; nt++) {
                int n = bn + wn * 32 + nt * 8 + 2 * lc;
                float2 v;
                v.x = acc[mt][nt][half_ * 2 + 0] + bo[n];
                v.y = acc[mt][nt][half_ * 2 + 1] + bo[n + 1];
                *(float2*)&out[(size_t)m * Dd + n] = v;
            }
        }
    }
}

// ============ Flash attention: fp16 QK^T + tf32 PV, 8 warps, DB, one barrier ====
// K tile: 32 tokens x 64 halves, stride KSH=72 halves (>= 64 ✓; banks 4lr+lc ✓).
// V tile: 32 tokens x 64 floats, stride VST=72 floats (>= 64 ✓, R11-proven class).
// P tile: 128 x 32 floats, stride PST=36 (>= 32 ✓).
#define KSH 72
#define VST 72
#define PST 36
#define KBUFH (32 * KSH)
#define VBUF  (32 * VST)

__global__ void __launch_bounds__(256)
attn_kernel()
{
    __shared__ __align__(16) __half Ks[2 * KBUFH];   //  9.2 KB
    __shared__ __align__(16) float  Vs[2 * VBUF];    // 18.4 KB
    __shared__ __align__(16) float  Ps[128 * PST];   // 18.4 KB  (total 46.0 KB)

    const int tid = threadIdx.x;
    const int lane = tid & 31, w = tid >> 5;
    const int lr = lane >> 2, lc = lane & 3;
    const int bh = blockIdx.y;
    const int qb = blockIdx.x * 128;

    const __half* Qg = g_qh + ((size_t)bh * Ss + qb) * DHd;
    const __half* Kg = g_kh + (size_t)bh * Ss * DHd;
    const float*  Vg = g_v  + (size_t)bh * Ss * DHd;

    // Q frags direct from gmem (fp16, already pre-scaled by 0.125)
    unsigned qf[4][4];
    {
        const __half* q0 = Qg + (w * 16 + lr) * DHd;
        #pragma unroll
        for (int ks = 0; ks < 4; ks++) {
            qf[ks][0] = ldu32(q0 + ks * 16 + 2 * lc);
            qf[ks][1] = ldu32(q0 + 8 * DHd + ks * 16 + 2 * lc);
            qf[ks][2] = ldu32(q0 + ks * 16 + 2 * lc + 8);
            qf[ks][3] = ldu32(q0 + 8 * DHd + ks * 16 + 2 * lc + 8);
        }
    }

    float acc_o[8][4] = {};
    float m0 = -1e30f, m1 = -1e30f, l0 = 0.f, l1 = 0.f;

    // prefetch tile 0: K = 32x64 halves (1 uint4/thread), V = 32x64 floats (2 float4/thread)
    uint4 pk;
    float4 pv[2];
    {
        int krow = tid >> 3, kc8 = (tid & 7) * 8;
        pk = *(const uint4*)&Kg[(size_t)krow * DHd + kc8];
        #pragma unroll
        for (int i = 0; i < 2; i++) {
            int f = tid + i * 256, row = f >> 4, c4 = (f & 15) * 4;
            pv[i] = *(const float4*)&Vg[row * DHd + c4];
        }
    }

    for (int kt = 0; kt < Ss; kt += 32) {
        const int buf = (kt >> 5) & 1;
        __half* ksm = Ks + buf * KBUFH;
        float*  vsm = Vs + buf * VBUF;

        {
            int krow = tid >> 3, kc8 = (tid & 7) * 8;
            *(uint4*)&ksm[krow * KSH + kc8] = pk;
            #pragma unroll
            for (int i = 0; i < 2; i++) {
                int f = tid + i * 256, row = f >> 4, c4 = (f & 15) * 4;
                *(float4*)&vsm[row * VST + c4] = pv[i];
            }
        }
        __syncthreads();   // single barrier (double-buffered)

        if (kt + 32 < Ss) {
            int krow = tid >> 3, kc8 = (tid & 7) * 8;
            pk = *(const uint4*)&Kg[(size_t)(kt + 32 + krow) * DHd + kc8];
            #pragma unroll
            for (int i = 0; i < 2; i++) {
                int f = tid + i * 256, row = f >> 4, c4 = (f & 15) * 4;
                pv[i] = *(const float4*)&Vg[(kt + 32 + row) * DHd + c4];
            }
        }

        // S = (Q/8) K^T   (fp16 MMA, 4 ksteps of 16)
        float s[4][4] = {};
        #pragma unroll
        for (int ks = 0; ks < 4; ks++) {
            #pragma unroll
            for (int nt = 0; nt < 4; nt++) {
                const __half* kp = ksm + (nt * 8 + lr) * KSH + ks * 16 + 2 * lc;
                mma_f16(s[nt], qf[ks][0], qf[ks][1], qf[ks][2], qf[ks][3],
                        ldu32(kp), ldu32(kp + 8));
            }
        }

        // online softmax (rows lr, lr+8)
        float mx0 = -1e30f, mx1 = -1e30f;
        #pragma unroll
        for (int nt = 0; nt < 4; nt++) {
            mx0 = fmaxf(mx0, fmaxf(s[nt][0], s[nt][1]));
            mx1 = fmaxf(mx1, fmaxf(s[nt][2], s[nt][3]));
        }
        mx0 = fmaxf(mx0, __shfl_xor_sync(0xffffffff, mx0, 1));
        mx0 = fmaxf(mx0, __shfl_xor_sync(0xffffffff, mx0, 2));
        mx1 = fmaxf(mx1, __shfl_xor_sync(0xffffffff, mx1, 1));
        mx1 = fmaxf(mx1, __shfl_xor_sync(0xffffffff, mx1, 2));

        float mn0 = fmaxf(m0, mx0), mn1 = fmaxf(m1, mx1);
        float cr0 = __expf(m0 - mn0), cr1 = __expf(m1 - mn1);
        m0 = mn0; m1 = mn1;

        float ls0 = 0.f, ls1 = 0.f;
        float* pp0 = Ps + (w * 16 + lr) * PST + 2 * lc;
        float* pp1 = pp0 + 8 * PST;
        #pragma unroll
        for (int nt = 0; nt < 4; nt++) {
            float p00 = __expf(s[nt][0] - m0), p01 = __expf(s[nt][1] - m0);
            float p10 = __expf(s[nt][2] - m1), p11 = __expf(s[nt][3] - m1);
            ls0 += p00 + p01; ls1 += p10 + p11;
            *(float2*)&pp0[nt * 8] = make_float2(f2tff(p00), f2tff(p01));
            *(float2*)&pp1[nt * 8] = make_float2(f2tff(p10), f2tff(p11));
        }
        ls0 += __shfl_xor_sync(0xffffffff, ls0, 1);
        ls0 += __shfl_xor_sync(0xffffffff, ls0, 2);
        ls1 += __shfl_xor_sync(0xffffffff, ls1, 1);
        ls1 += __shfl_xor_sync(0xffffffff, ls1, 2);
        l0 = l0 * cr0 + ls0;
        l1 = l1 * cr1 + ls1;

        #pragma unroll
        for (int dt = 0; dt < 8; dt++) {
            acc_o[dt][0] *= cr0; acc_o[dt][1] *= cr0;
            acc_o[dt][2] *= cr1; acc_o[dt][3] *= cr1;
        }
        __syncwarp();

        // O += P V   (tf32 MMA, proven path)
        #pragma unroll
        for (int ks = 0; ks < 4; ks++) {
            const float* pf = Ps + (w * 16 + lr) * PST + ks * 8 + lc;
            unsigned a0 = su(pf[0]), a1 = su(pf[8 * PST]);
            unsigned a2 = su(pf[4]), a3 = su(pf[8 * PST + 4]);
            #pragma unroll
            for (int dt = 0; dt < 8; dt++) {
                const float* vp = vsm + (ks * 8 + lc) * VST + dt * 8 + lr;
                mma_tf32(acc_o[dt], a0, a1, a2, a3, su(vp[0]), su(vp[4 * VST]));
            }
        }
        // no trailing barrier (double-buffered)
    }

    const float inv0 = 1.f / l0, inv1 = 1.f / l1;
    const int b = bh >> 4, h = bh & 15;
    const int r0 = b * Ss + qb + w * 16 + lr;
    #pragma unroll
    for (int dt = 0; dt < 8; dt++) {
        int col = h * DHd + dt * 8 + 2 * lc;
        *(__half2*)&g_ctxh[(size_t)r0 * Dd + col] =
            __floats2half2_rn(acc_o[dt][0] * inv0, acc_o[dt][1] * inv0);
        *(__half2*)&g_ctxh[(size_t)(r0 + 8) * Dd + col] =
            __floats2half2_rn(acc_o[dt][2] * inv1, acc_o[dt][3] * inv1);
    }
}

// ============ launch ============
extern "C" void kernel_launch(void* const* d_in, const int* in_sizes, int n_in,
                              void* d_out, int out_size)
{
    const float* x  = (const float*)d_in[0];
    const float* Wq = (const float*)d_in[1];
    const float* bq = (const float*)d_in[2];
    const float* Wk = (const float*)d_in[3];
    const float* bk = (const float*)d_in[4];
    const float* Wv = (const float*)d_in[5];
    const float* bv = (const float*)d_in[6];
    const float* Wo = (const float*)d_in[7];
    const float* bo = (const float*)d_in[8];
    float* out = (float*)d_out;

    const int total = X4 + 4 * W4;
    cvt_inputs<<<(total + 255) / 256, 256>>>((const float4*)x, (const float4*)Wq,
                                             (const float4*)Wk, (const float4*)Wv,
                                             (const float4*)Wo);

    dim3 gQKV(Dd / 128, Mm / 128, 3);
    qkv_kernel<<<gQKV, 256>>>(bq, bk, bv);

    dim3 gAtt(Ss / 128, Bb * Hh);
    attn_kernel<<<gAtt, 256>>>();

    dim3 gO(Dd / 128, Mm / 128);
    oproj_kernel<<<gO, 256>>>(bo, out);
}

// round 13
// speedup vs baseline: 1.7517x; 1.1529x over previous
#include <cuda_runtime.h>
#include <cuda_fp16.h>
#include <cstdint>

#define Bb 4
#define Ss 2048
#define Dd 1024
#define Hh 16
#define DHd 64
#define Mm (Bb*Ss)   // 8192

// Scratch (allocation-free)
__device__ __half g_xh [(size_t)Mm*Dd];
__device__ __half g_wqh[(size_t)Dd*Dd];
__device__ __half g_wkh[(size_t)Dd*Dd];
__device__ __half g_wvh[(size_t)Dd*Dd];
__device__ __half g_woh[(size_t)Dd*Dd];
__device__ __half g_qh [(size_t)Bb*Hh*Ss*DHd];   // q, pre-scaled by 0.125, fp16
__device__ __half g_kh [(size_t)Bb*Hh*Ss*DHd];   // k, fp16
__device__ __half g_vt [(size_t)Bb*Hh*DHd*Ss];   // V TRANSPOSED [b,h,d,s], fp16
__device__ __half g_ctxh[(size_t)Mm*Dd];

__device__ __forceinline__ unsigned su(float f) { return __float_as_uint(f); }
__device__ __forceinline__ unsigned ldu32(const __half* p) {
    return *(const unsigned*)p;
}

__device__ __forceinline__ void mma_f16(float* c, unsigned a0, unsigned a1,
                                        unsigned a2, unsigned a3,
                                        unsigned b0, unsigned b1) {
    asm volatile(
        "mma.sync.aligned.m16n8k16.row.col.f32.f16.f16.f32 "
        "{%0,%1,%2,%3},{%4,%5,%6,%7},{%8,%9},{%0,%1,%2,%3};"
        : "+f"(c[0]), "+f"(c[1]), "+f"(c[2]), "+f"(c[3])
        : "r"(a0), "r"(a1), "r"(a2), "r"(a3), "r"(b0), "r"(b1));
}

// ============ input conversion: fp32 -> fp16 (direct symbol writes) ============
#define X4 (Mm*Dd/4)
#define W4 (Dd*Dd/4)

__global__ void cvt_inputs(const float4* __restrict__ x,
                           const float4* __restrict__ wq,
                           const float4* __restrict__ wk,
                           const float4* __restrict__ wv,
                           const float4* __restrict__ wo)
{
    int i = blockIdx.x * blockDim.x + threadIdx.x;
    const float4* src; __half2* dst; int j;
    if (i < X4)              { src = x;  dst = (__half2*)g_xh;  j = i; }
    else if (i < X4 + W4)    { src = wq; dst = (__half2*)g_wqh; j = i - X4; }
    else if (i < X4 + 2*W4)  { src = wk; dst = (__half2*)g_wkh; j = i - X4 - W4; }
    else if (i < X4 + 3*W4)  { src = wv; dst = (__half2*)g_wvh; j = i - X4 - 2*W4; }
    else if (i < X4 + 4*W4)  { src = wo; dst = (__half2*)g_woh; j = i - X4 - 3*W4; }
    else return;
    float4 v = src[j];
    dst[2 * j]     = __floats2half2_rn(v.x, v.y);
    dst[2 * j + 1] = __floats2half2_rn(v.z, v.w);
}

// ============ FP16 GEMM core (R11/R12-proven: DB smem, one barrier/K-step) ======
#define SH 40
#define BUFH (128 * SH)

__device__ __forceinline__ void gemm_core_f16(
    const __half* __restrict__ A, const __half* __restrict__ W,
    __half* As, __half* Bs, int bm, int bn, float acc[4][4][4])
{
    const int tid = threadIdx.x;
    const int lane = tid & 31, wid = tid >> 5;
    const int wm = wid >> 2, wn = wid & 3;
    const int lr = lane >> 2, lc = lane & 3;

    const int row = tid >> 1;
    const int cs  = (tid & 1) * 16;

    uint4 pa0, pa1, pb0, pb1;
    pa0 = *(const uint4*)&A[(size_t)(bm + row) * Dd + cs];
    pa1 = *(const uint4*)&A[(size_t)(bm + row) * Dd + cs + 8];
    pb0 = *(const uint4*)&W[(size_t)(bn + row) * Dd + cs];
    pb1 = *(const uint4*)&W[(size_t)(bn + row) * Dd + cs + 8];

    for (int k0 = 0; k0 < Dd; k0 += 32) {
        const int buf = (k0 >> 5) & 1;
        __half* as = As + buf * BUFH;
        __half* bs = Bs + buf * BUFH;

        *(uint4*)&as[row * SH + cs]     = pa0;
        *(uint4*)&as[row * SH + cs + 8] = pa1;
        *(uint4*)&bs[row * SH + cs]     = pb0;
        *(uint4*)&bs[row * SH + cs + 8] = pb1;
        __syncthreads();

        if (k0 + 32 < Dd) {
            pa0 = *(const uint4*)&A[(size_t)(bm + row) * Dd + k0 + 32 + cs];
            pa1 = *(const uint4*)&A[(size_t)(bm + row) * Dd + k0 + 32 + cs + 8];
            pb0 = *(const uint4*)&W[(size_t)(bn + row) * Dd + k0 + 32 + cs];
            pb1 = *(const uint4*)&W[(size_t)(bn + row) * Dd + k0 + 32 + cs + 8];
        }

        #pragma unroll
        for (int ks = 0; ks < 2; ks++) {
            unsigned af[4][4], bf[4][2];
            #pragma unroll
            for (int mt = 0; mt < 4; mt++) {
                const __half* Ab = as + (wm * 64 + mt * 16 + lr) * SH + ks * 16 + 2 * lc;
                af[mt][0] = ldu32(Ab);
                af[mt][1] = ldu32(Ab + 8 * SH);
                af[mt][2] = ldu32(Ab + 8);
                af[mt][3] = ldu32(Ab + 8 * SH + 8);
            }
            #pragma unroll
            for (int nt = 0; nt < 4; nt++) {
                const __half* Bp = bs + (wn * 32 + nt * 8 + lr) * SH + ks * 16 + 2 * lc;
                bf[nt][0] = ldu32(Bp);
                bf[nt][1] = ldu32(Bp + 8);
            }
            #pragma unroll
            for (int mt = 0; mt < 4; mt++)
                #pragma unroll
                for (int nt = 0; nt < 4; nt++)
                    mma_f16(acc[mt][nt], af[mt][0], af[mt][1], af[mt][2], af[mt][3],
                            bf[nt][0], bf[nt][1]);
        }
    }
}

// ============ QKV projection (q,k -> fp16; v -> fp16 TRANSPOSED) ============
__global__ void __launch_bounds__(256)
qkv_kernel(const float* __restrict__ bq, const float* __restrict__ bk,
           const float* __restrict__ bv)
{
    __shared__ __align__(16) __half As[2 * BUFH];
    __shared__ __align__(16) __half Bs[2 * BUFH];

    const __half* W; const float* bias; const int which = blockIdx.z;
    if (which == 0)      { W = g_wqh; bias = bq; }
    else if (which == 1) { W = g_wkh; bias = bk; }
    else                 { W = g_wvh; bias = bv; }

    const int bm = blockIdx.y * 128, bn = blockIdx.x * 128;
    float acc[4][4][4] = {};
    gemm_core_f16(g_xh, W, As, Bs, bm, bn, acc);

    const int lane = threadIdx.x & 31, wid = threadIdx.x >> 5;
    const int wm = wid >> 2, wn = wid & 3;
    const int lr = lane >> 2, lc = lane & 3;

    #pragma unroll
    for (int mt = 0; mt < 4; mt++) {
        #pragma unroll
        for (int half_ = 0; half_ < 2; half_++) {
            int m = bm + wm * 64 + mt * 16 + lr + half_ * 8;
            int b = m >> 11, s = m & 2047;
            #pragma unroll
            for (int nt = 0; nt < 4; nt++) {
                int n = bn + wn * 32 + nt * 8 + 2 * lc;
                int h = n >> 6, d = n & 63;
                float vx = acc[mt][nt][half_ * 2 + 0] + bias[n];
                float vy = acc[mt][nt][half_ * 2 + 1] + bias[n + 1];
                if (which == 0) {
                    size_t idx = ((size_t)((b * Hh + h) * Ss + s)) * DHd + d;
                    *(__half2*)&g_qh[idx] = __floats2half2_rn(0.125f * vx, 0.125f * vy);
                } else if (which == 1) {
                    size_t idx = ((size_t)((b * Hh + h) * Ss + s)) * DHd + d;
                    *(__half2*)&g_kh[idx] = __floats2half2_rn(vx, vy);
                } else {
                    // V transposed: [b,h,d,s]
                    size_t base = ((size_t)(b * Hh + h) * DHd + d) * Ss + s;
                    g_vt[base]      = __float2half_rn(vx);
                    g_vt[base + Ss] = __float2half_rn(vy);
                }
            }
        }
    }
}

// ============ Output projection (R11-proven) ============
__global__ void __launch_bounds__(256)
oproj_kernel(const float* __restrict__ bo, float* __restrict__ out)
{
    __shared__ __align__(16) __half As[2 * BUFH];
    __shared__ __align__(16) __half Bs[2 * BUFH];

    const int bm = blockIdx.y * 128, bn = blockIdx.x * 128;
    float acc[4][4][4] = {};
    gemm_core_f16(g_ctxh, g_woh, As, Bs, bm, bn, acc);

    const int lane = threadIdx.x & 31, wid = threadIdx.x >> 5;
    const int wm = wid >> 2, wn = wid & 3;
    const int lr = lane >> 2, lc = lane & 3;

    #pragma unroll
    for (int mt = 0; mt < 4; mt++) {
        #pragma unroll
        for (int half_ = 0; half_ < 2; half_++) {
            int m = bm + wm * 64 + mt * 16 + lr + half_ * 8;
            #pragma unroll
            for (int nt = 0; nt < 4; nt++) {
                int n = bn + wn * 32 + nt * 8 + 2 * lc;
                float2 v;
                v.x = acc[mt][nt][half_ * 2 + 0] + bo[n];
                v.y = acc[mt][nt][half_ * 2 + 1] + bo[n + 1];
                *(float2*)&out[(size_t)m * Dd + n] = v;
            }
        }
    }
}

// ============ Flash attention: ALL-fp16 MMA, 8 warps, DB, one barrier ============
// K tile:  32 tok x 64 halves, stride KSH=72 (>=64 ✓).
// V^T tile: 64 dim x 32 halves, stride VSH=40 (>=32 ✓; frag banks 20r+lc distinct ✓).
// P tile:  128 q x 32 halves,  stride PSH=40 (>=32 ✓).
#define KSH 72
#define VSH 40
#define PSH 40
#define KBUFH (32 * KSH)
#define VBUFH (64 * VSH)

__global__ void __launch_bounds__(256)
attn_kernel()
{
    __shared__ __align__(16) __half Ks[2 * KBUFH];   //  9.2 KB
    __shared__ __align__(16) __half Vs[2 * VBUFH];   // 10.2 KB
    __shared__ __align__(16) __half Ps[128 * PSH];   // 10.2 KB  (total 29.7 KB)

    const int tid = threadIdx.x;
    const int lane = tid & 31, w = tid >> 5;
    const int lr = lane >> 2, lc = lane & 3;
    const int bh = blockIdx.y;
    const int qb = blockIdx.x * 128;

    const __half* Qg = g_qh + ((size_t)bh * Ss + qb) * DHd;
    const __half* Kg = g_kh + (size_t)bh * Ss * DHd;
    const __half* Vg = g_vt + (size_t)bh * DHd * Ss;   // [dim][token]

    // Q frags direct from gmem (fp16, already pre-scaled by 0.125)
    unsigned qf[4][4];
    {
        const __half* q0 = Qg + (w * 16 + lr) * DHd;
        #pragma unroll
        for (int ks = 0; ks < 4; ks++) {
            qf[ks][0] = ldu32(q0 + ks * 16 + 2 * lc);
            qf[ks][1] = ldu32(q0 + 8 * DHd + ks * 16 + 2 * lc);
            qf[ks][2] = ldu32(q0 + ks * 16 + 2 * lc + 8);
            qf[ks][3] = ldu32(q0 + 8 * DHd + ks * 16 + 2 * lc + 8);
        }
    }

    float acc_o[8][4] = {};
    float m0 = -1e30f, m1 = -1e30f, l0 = 0.f, l1 = 0.f;

    // prefetch tile 0: K = 32x64 halves (1 uint4/thread), V^T = 64x32 halves (1 uint4/thread)
    uint4 pk, pv;
    {
        int krow = tid >> 3, kc8 = (tid & 7) * 8;
        pk = *(const uint4*)&Kg[(size_t)krow * DHd + kc8];
        int vrow = tid >> 2, vc8 = (tid & 3) * 8;
        pv = *(const uint4*)&Vg[(size_t)vrow * Ss + vc8];
    }

    for (int kt = 0; kt < Ss; kt += 32) {
        const int buf = (kt >> 5) & 1;
        __half* ksm = Ks + buf * KBUFH;
        __half* vsm = Vs + buf * VBUFH;

        {
            int krow = tid >> 3, kc8 = (tid & 7) * 8;
            *(uint4*)&ksm[krow * KSH + kc8] = pk;
            int vrow = tid >> 2, vc8 = (tid & 3) * 8;
            *(uint4*)&vsm[vrow * VSH + vc8] = pv;
        }
        __syncthreads();   // single barrier (double-buffered)

        if (kt + 32 < Ss) {
            int krow = tid >> 3, kc8 = (tid & 7) * 8;
            pk = *(const uint4*)&Kg[(size_t)(kt + 32 + krow) * DHd + kc8];
            int vrow = tid >> 2, vc8 = (tid & 3) * 8;
            pv = *(const uint4*)&Vg[(size_t)vrow * Ss + kt + 32 + vc8];
        }

        // S = (Q/8) K^T   (fp16 MMA, 4 ksteps of 16)
        float s[4][4] = {};
        #pragma unroll
        for (int ks = 0; ks < 4; ks++) {
            #pragma unroll
            for (int nt = 0; nt < 4; nt++) {
                const __half* kp = ksm + (nt * 8 + lr) * KSH + ks * 16 + 2 * lc;
                mma_f16(s[nt], qf[ks][0], qf[ks][1], qf[ks][2], qf[ks][3],
                        ldu32(kp), ldu32(kp + 8));
            }
        }

        // online softmax (rows lr, lr+8)
        float mx0 = -1e30f, mx1 = -1e30f;
        #pragma unroll
        for (int nt = 0; nt < 4; nt++) {
            mx0 = fmaxf(mx0, fmaxf(s[nt][0], s[nt][1]));
            mx1 = fmaxf(mx1, fmaxf(s[nt][2], s[nt][3]));
        }
        mx0 = fmaxf(mx0, __shfl_xor_sync(0xffffffff, mx0, 1));
        mx0 = fmaxf(mx0, __shfl_xor_sync(0xffffffff, mx0, 2));
        mx1 = fmaxf(mx1, __shfl_xor_sync(0xffffffff, mx1, 1));
        mx1 = fmaxf(mx1, __shfl_xor_sync(0xffffffff, mx1, 2));

        float mn0 = fmaxf(m0, mx0), mn1 = fmaxf(m1, mx1);
        float cr0 = __expf(m0 - mn0), cr1 = __expf(m1 - mn1);
        m0 = mn0; m1 = mn1;

        float ls0 = 0.f, ls1 = 0.f;
        __half* pp0 = Ps + (w * 16 + lr) * PSH + 2 * lc;
        __half* pp1 = pp0 + 8 * PSH;
        #pragma unroll
        for (int nt = 0; nt < 4; nt++) {
            float p00 = __expf(s[nt][0] - m0), p01 = __expf(s[nt][1] - m0);
            float p10 = __expf(s[nt][2] - m1), p11 = __expf(s[nt][3] - m1);
            ls0 += p00 + p01; ls1 += p10 + p11;
            *(__half2*)&pp0[nt * 8] = __floats2half2_rn(p00, p01);
            *(__half2*)&pp1[nt * 8] = __floats2half2_rn(p10, p11);
        }
        ls0 += __shfl_xor_sync(0xffffffff, ls0, 1);
        ls0 += __shfl_xor_sync(0xffffffff, ls0, 2);
        ls1 += __shfl_xor_sync(0xffffffff, ls1, 1);
        ls1 += __shfl_xor_sync(0xffffffff, ls1, 2);
        l0 = l0 * cr0 + ls0;
        l1 = l1 * cr1 + ls1;

        #pragma unroll
        for (int dt = 0; dt < 8; dt++) {
            acc_o[dt][0] *= cr0; acc_o[dt][1] *= cr0;
            acc_o[dt][2] *= cr1; acc_o[dt][3] *= cr1;
        }
        __syncwarp();

        // O += P V   (fp16 MMA, 2 ksteps of 16 tokens)
        #pragma unroll
        for (int ks = 0; ks < 2; ks++) {
            const __half* pf = Ps + (w * 16 + lr) * PSH + ks * 16 + 2 * lc;
            unsigned a0 = ldu32(pf),     a1 = ldu32(pf + 8 * PSH);
            unsigned a2 = ldu32(pf + 8), a3 = ldu32(pf + 8 * PSH + 8);
            #pragma unroll
            for (int dt = 0; dt < 8; dt++) {
                const __half* vp = vsm + (dt * 8 + lr) * VSH + ks * 16 + 2 * lc;
                mma_f16(acc_o[dt], a0, a1, a2, a3, ldu32(vp), ldu32(vp + 8));
            }
        }
        __syncwarp();   // P reads done before next iteration overwrites Ps
    }

    const float inv0 = 1.f / l0, inv1 = 1.f / l1;
    const int b = bh >> 4, h = bh & 15;
    const int r0 = b * Ss + qb + w * 16 + lr;
    #pragma unroll
    for (int dt = 0; dt < 8; dt++) {
        int col = h * DHd + dt * 8 + 2 * lc;
        *(__half2*)&g_ctxh[(size_t)r0 * Dd + col] =
            __floats2half2_rn(acc_o[dt][0] * inv0, acc_o[dt][1] * inv0);
        *(__half2*)&g_ctxh[(size_t)(r0 + 8) * Dd + col] =
            __floats2half2_rn(acc_o[dt][2] * inv1, acc_o[dt][3] * inv1);
    }
}

// ============ launch ============
extern "C" void kernel_launch(void* const* d_in, const int* in_sizes, int n_in,
                              void* d_out, int out_size)
{
    const float* x  = (const float*)d_in[0];
    const float* Wq = (const float*)d_in[1];
    const float* bq = (const float*)d_in[2];
    const float* Wk = (const float*)d_in[3];
    const float* bk = (const float*)d_in[4];
    const float* Wv = (const float*)d_in[5];
    const float* bv = (const float*)d_in[6];
    const float* Wo = (const float*)d_in[7];
    const float* bo = (const float*)d_in[8];
    float* out = (float*)d_out;

    const int total = X4 + 4 * W4;
    cvt_inputs<<<(total + 255) / 256, 256>>>((const float4*)x, (const float4*)Wq,
                                             (const float4*)Wk, (const float4*)Wv,
                                             (const float4*)Wo);

    dim3 gQKV(Dd / 128, Mm / 128, 3);
    qkv_kernel<<<gQKV, 256>>>(bq, bk, bv);

    dim3 gAtt(Ss / 128, Bb * Hh);
    attn_kernel<<<gAtt, 256>>>();

    dim3 gO(Dd / 128, Mm / 128);
    oproj_kernel<<<gO, 256>>>(bo, out);
}

// round 15
// speedup vs baseline: 2.0365x; 1.1626x over previous
#include <cuda_runtime.h>
#include <cuda_fp16.h>
#include <cstdint>

#define Bb 4
#define Ss 2048
#define Dd 1024
#define Hh 16
#define DHd 64
#define Mm (Bb*Ss)   // 8192

// Scratch (allocation-free)
__device__ __half g_xh [(size_t)Mm*Dd];
__device__ __half g_wqh[(size_t)Dd*Dd];
__device__ __half g_wkh[(size_t)Dd*Dd];
__device__ __half g_wvh[(size_t)Dd*Dd];
__device__ __half g_woh[(size_t)Dd*Dd];
__device__ __half g_qh [(size_t)Bb*Hh*Ss*DHd];   // q, pre-scaled by 0.125, fp16
__device__ __half g_kh [(size_t)Bb*Hh*Ss*DHd];   // k, fp16
__device__ __half g_vt [(size_t)Bb*Hh*DHd*Ss];   // V TRANSPOSED [b,h,d,s], fp16
__device__ __half g_ctxh[(size_t)Mm*Dd];

__device__ __forceinline__ unsigned ldu32(const __half* p) {
    return *(const unsigned*)p;
}

__device__ __forceinline__ void mma_f16(float* c, unsigned a0, unsigned a1,
                                        unsigned a2, unsigned a3,
                                        unsigned b0, unsigned b1) {
    asm volatile(
        "mma.sync.aligned.m16n8k16.row.col.f32.f16.f16.f32 "
        "{%0,%1,%2,%3},{%4,%5,%6,%7},{%8,%9},{%0,%1,%2,%3};"
        : "+f"(c[0]), "+f"(c[1]), "+f"(c[2]), "+f"(c[3])
        : "r"(a0), "r"(a1), "r"(a2), "r"(a3), "r"(b0), "r"(b1));
}

__device__ __forceinline__ void cp16(unsigned dst, const void* src) {
    asm volatile("cp.async.cg.shared.global [%0], [%1], 16;"
                 :: "r"(dst), "l"(src) : "memory");
}
__device__ __forceinline__ void cp_commit() {
    asm volatile("cp.async.commit_group;" ::: "memory");
}
__device__ __forceinline__ void cp_wait1() {
    asm volatile("cp.async.wait_group 1;" ::: "memory");
}

// ============ input conversion: fp32 -> fp16 (direct symbol writes) ============
#define X4 (Mm*Dd/4)
#define W4 (Dd*Dd/4)

__global__ void cvt_inputs(const float4* __restrict__ x,
                           const float4* __restrict__ wq,
                           const float4* __restrict__ wk,
                           const float4* __restrict__ wv,
                           const float4* __restrict__ wo)
{
    int i = blockIdx.x * blockDim.x + threadIdx.x;
    const float4* src; __half2* dst; int j;
    if (i < X4)              { src = x;  dst = (__half2*)g_xh;  j = i; }
    else if (i < X4 + W4)    { src = wq; dst = (__half2*)g_wqh; j = i - X4; }
    else if (i < X4 + 2*W4)  { src = wk; dst = (__half2*)g_wkh; j = i - X4 - W4; }
    else if (i < X4 + 3*W4)  { src = wv; dst = (__half2*)g_wvh; j = i - X4 - 2*W4; }
    else if (i < X4 + 4*W4)  { src = wo; dst = (__half2*)g_woh; j = i - X4 - 3*W4; }
    else return;
    float4 v = src[j];
    dst[2 * j]     = __floats2half2_rn(v.x, v.y);
    dst[2 * j + 1] = __floats2half2_rn(v.z, v.w);
}

// ============ FP16 GEMM core: cp.async 3-stage pipeline, BK=32 ============
// Row = 32 halves (64 B), stride SH=40 halves (80 B, 16B-multiple). Frag
// addressing identical to the R11/R12/R13-proven layout -> bit-identical math.
#define SH 40
#define STG (128 * SH)          // halves per stage per matrix
#define GEMM_SMEM (6 * STG * 2) // bytes: 3 stages x (A+B) = 61440

__device__ __forceinline__ void gemm_issue(
    const __half* __restrict__ A, const __half* __restrict__ W,
    unsigned as0, unsigned bs0, int s, int bm, int bn, int k0, int tid)
{
    #pragma unroll
    for (int i = 0; i < 2; i++) {
        int idx = tid + i * 256;
        int row = idx >> 2, c8 = (idx & 3) * 8;
        unsigned off = (s * STG + row * SH + c8) * 2;
        cp16(as0 + off, &A[(size_t)(bm + row) * Dd + k0 + c8]);
        cp16(bs0 + off, &W[(size_t)(bn + row) * Dd + k0 + c8]);
    }
}

__device__ __forceinline__ void gemm_core_f16(
    const __half* __restrict__ A, const __half* __restrict__ W,
    __half* As, __half* Bs, int bm, int bn, float acc[4][4][4])
{
    const int tid = threadIdx.x;
    const int lane = tid & 31, wid = tid >> 5;
    const int wm = wid >> 2, wn = wid & 3;
    const int lr = lane >> 2, lc = lane & 3;

    const unsigned as0 = (unsigned)__cvta_generic_to_shared(As);
    const unsigned bs0 = (unsigned)__cvta_generic_to_shared(Bs);

    // prologue: stages 0 and 1
    gemm_issue(A, W, as0, bs0, 0, bm, bn, 0, tid);
    cp_commit();
    gemm_issue(A, W, as0, bs0, 1, bm, bn, 32, tid);
    cp_commit();

    int it = 0;
    for (int k0 = 0; k0 < Dd; k0 += 32, it++) {
        const int buf = it % 3;
        cp_wait1();          // stages <= it complete
        __syncthreads();

        if (k0 + 64 < Dd)
            gemm_issue(A, W, as0, bs0, (it + 2) % 3, bm, bn, k0 + 64, tid);
        cp_commit();         // uniform group accounting (may be empty)

        const __half* as = As + buf * STG;
        const __half* bs = Bs + buf * STG;

        #pragma unroll
        for (int ks = 0; ks < 2; ks++) {
            unsigned af[4][4], bf[4][2];
            #pragma unroll
            for (int mt = 0; mt < 4; mt++) {
                const __half* Ab = as + (wm * 64 + mt * 16 + lr) * SH + ks * 16 + 2 * lc;
                af[mt][0] = ldu32(Ab);
                af[mt][1] = ldu32(Ab + 8 * SH);
                af[mt][2] = ldu32(Ab + 8);
                af[mt][3] = ldu32(Ab + 8 * SH + 8);
            }
            #pragma unroll
            for (int nt = 0; nt < 4; nt++) {
                const __half* Bp = bs + (wn * 32 + nt * 8 + lr) * SH + ks * 16 + 2 * lc;
                bf[nt][0] = ldu32(Bp);
                bf[nt][1] = ldu32(Bp + 8);
            }
            #pragma unroll
            for (int mt = 0; mt < 4; mt++)
                #pragma unroll
                for (int nt = 0; nt < 4; nt++)
                    mma_f16(acc[mt][nt], af[mt][0], af[mt][1], af[mt][2], af[mt][3],
                            bf[nt][0], bf[nt][1]);
        }
        // no trailing barrier: stage issued in iter i+1 targets buffer read in
        // iter i-? — writes to buffer (it+2)%3 are fenced by the NEXT iteration's
        // barrier, which follows this iteration's reads of that buffer... (reads
        // of buf (it+2)%3 happened in iter it-1, fenced by iter it's barrier ✓)
    }
}

// ============ QKV projection (q,k -> fp16; v -> fp16 TRANSPOSED) ============
__global__ void __launch_bounds__(256)
qkv_kernel(const float* __restrict__ bq, const float* __restrict__ bk,
           const float* __restrict__ bv)
{
    extern __shared__ __align__(16) __half dsm[];
    __half* As = dsm;
    __half* Bs = dsm + 3 * STG;

    const __half* W; const float* bias; const int which = blockIdx.z;
    if (which == 0)      { W = g_wqh; bias = bq; }
    else if (which == 1) { W = g_wkh; bias = bk; }
    else                 { W = g_wvh; bias = bv; }

    const int bm = blockIdx.y * 128, bn = blockIdx.x * 128;
    float acc[4][4][4] = {};
    gemm_core_f16(g_xh, W, As, Bs, bm, bn, acc);

    const int lane = threadIdx.x & 31, wid = threadIdx.x >> 5;
    const int wm = wid >> 2, wn = wid & 3;
    const int lr = lane >> 2, lc = lane & 3;

    #pragma unroll
    for (int mt = 0; mt < 4; mt++) {
        #pragma unroll
        for (int half_ = 0; half_ < 2; half_++) {
            int m = bm + wm * 64 + mt * 16 + lr + half_ * 8;
            int b = m >> 11, s = m & 2047;
            #pragma unroll
            for (int nt = 0; nt < 4; nt++) {
                int n = bn + wn * 32 + nt * 8 + 2 * lc;
                int h = n >> 6, d = n & 63;
                float vx = acc[mt][nt][half_ * 2 + 0] + bias[n];
                float vy = acc[mt][nt][half_ * 2 + 1] + bias[n + 1];
                if (which == 0) {
                    size_t idx = ((size_t)((b * Hh + h) * Ss + s)) * DHd + d;
                    *(__half2*)&g_qh[idx] = __floats2half2_rn(0.125f * vx, 0.125f * vy);
                } else if (which == 1) {
                    size_t idx = ((size_t)((b * Hh + h) * Ss + s)) * DHd + d;
                    *(__half2*)&g_kh[idx] = __floats2half2_rn(vx, vy);
                } else {
                    size_t base = ((size_t)(b * Hh + h) * DHd + d) * Ss + s;
                    g_vt[base]      = __float2half_rn(vx);
                    g_vt[base + Ss] = __float2half_rn(vy);
                }
            }
        }
    }
}

// ============ Output projection ============
__global__ void __launch_bounds__(256)
oproj_kernel(const float* __restrict__ bo, float* __restrict__ out)
{
    extern __shared__ __align__(16) __half dsm[];
    __half* As = dsm;
    __half* Bs = dsm + 3 * STG;

    const int bm = blockIdx.y * 128, bn = blockIdx.x * 128;
    float acc[4][4][4] = {};
    gemm_core_f16(g_ctxh, g_woh, As, Bs, bm, bn, acc);

    const int lane = threadIdx.x & 31, wid = threadIdx.x >> 5;
    const int wm = wid >> 2, wn = wid & 3;
    const int lr = lane >> 2, lc = lane & 3;

    #pragma unroll
    for (int mt = 0; mt < 4; mt++) {
        #pragma unroll
        for (int half_ = 0; half_ < 2; half_++) {
            int m = bm + wm * 64 + mt * 16 + lr + half_ * 8;
            #pragma unroll
            for (int nt = 0; nt < 4; nt++) {
                int n = bn + wn * 32 + nt * 8 + 2 * lc;
                float2 v;
                v.x = acc[mt][nt][half_ * 2 + 0] + bo[n];
                v.y = acc[mt][nt][half_ * 2 + 1] + bo[n + 1];
                *(float2*)&out[(size_t)m * Dd + n] = v;
            }
        }
    }
}

// ============ Flash attention: R13 verbatim (ALL-fp16 MMA, 8 warps, DB) ============
#define KSH 72
#define VSH 40
#define PSH 40
#define KBUFH (32 * KSH)
#define VBUFH (64 * VSH)

__global__ void __launch_bounds__(256)
attn_kernel()
{
    __shared__ __align__(16) __half Ks[2 * KBUFH];
    __shared__ __align__(16) __half Vs[2 * VBUFH];
    __shared__ __align__(16) __half Ps[128 * PSH];

    const int tid = threadIdx.x;
    const int lane = tid & 31, w = tid >> 5;
    const int lr = lane >> 2, lc = lane & 3;
    const int bh = blockIdx.y;
    const int qb = blockIdx.x * 128;

    const __half* Qg = g_qh + ((size_t)bh * Ss + qb) * DHd;
    const __half* Kg = g_kh + (size_t)bh * Ss * DHd;
    const __half* Vg = g_vt + (size_t)bh * DHd * Ss;

    unsigned qf[4][4];
    {
        const __half* q0 = Qg + (w * 16 + lr) * DHd;
        #pragma unroll
        for (int ks = 0; ks < 4; ks++) {
            qf[ks][0] = ldu32(q0 + ks * 16 + 2 * lc);
            qf[ks][1] = ldu32(q0 + 8 * DHd + ks * 16 + 2 * lc);
            qf[ks][2] = ldu32(q0 + ks * 16 + 2 * lc + 8);
            qf[ks][3] = ldu32(q0 + 8 * DHd + ks * 16 + 2 * lc + 8);
        }
    }

    float acc_o[8][4] = {};
    float m0 = -1e30f, m1 = -1e30f, l0 = 0.f, l1 = 0.f;

    uint4 pk, pv;
    {
        int krow = tid >> 3, kc8 = (tid & 7) * 8;
        pk = *(const uint4*)&Kg[(size_t)krow * DHd + kc8];
        int vrow = tid >> 2, vc8 = (tid & 3) * 8;
        pv = *(const uint4*)&Vg[(size_t)vrow * Ss + vc8];
    }

    for (int kt = 0; kt < Ss; kt += 32) {
        const int buf = (kt >> 5) & 1;
        __half* ksm = Ks + buf * KBUFH;
        __half* vsm = Vs + buf * VBUFH;

        {
            int krow = tid >> 3, kc8 = (tid & 7) * 8;
            *(uint4*)&ksm[krow * KSH + kc8] = pk;
            int vrow = tid >> 2, vc8 = (tid & 3) * 8;
            *(uint4*)&vsm[vrow * VSH + vc8] = pv;
        }
        __syncthreads();

        if (kt + 32 < Ss) {
            int krow = tid >> 3, kc8 = (tid & 7) * 8;
            pk = *(const uint4*)&Kg[(size_t)(kt + 32 + krow) * DHd + kc8];
            int vrow = tid >> 2, vc8 = (tid & 3) * 8;
            pv = *(const uint4*)&Vg[(size_t)vrow * Ss + kt + 32 + vc8];
        }

        float s[4][4] = {};
        #pragma unroll
        for (int ks = 0; ks < 4; ks++) {
            #pragma unroll
            for (int nt = 0; nt < 4; nt++) {
                const __half* kp = ksm + (nt * 8 + lr) * KSH + ks * 16 + 2 * lc;
                mma_f16(s[nt], qf[ks][0], qf[ks][1], qf[ks][2], qf[ks][3],
                        ldu32(kp), ldu32(kp + 8));
            }
        }

        float mx0 = -1e30f, mx1 = -1e30f;
        #pragma unroll
        for (int nt = 0; nt < 4; nt++) {
            mx0 = fmaxf(mx0, fmaxf(s[nt][0], s[nt][1]));
            mx1 = fmaxf(mx1, fmaxf(s[nt][2], s[nt][3]));
        }
        mx0 = fmaxf(mx0, __shfl_xor_sync(0xffffffff, mx0, 1));
        mx0 = fmaxf(mx0, __shfl_xor_sync(0xffffffff, mx0, 2));
        mx1 = fmaxf(mx1, __shfl_xor_sync(0xffffffff, mx1, 1));
        mx1 = fmaxf(mx1, __shfl_xor_sync(0xffffffff, mx1, 2));

        float mn0 = fmaxf(m0, mx0), mn1 = fmaxf(m1, mx1);
        float cr0 = __expf(m0 - mn0), cr1 = __expf(m1 - mn1);
        m0 = mn0; m1 = mn1;

        float ls0 = 0.f, ls1 = 0.f;
        __half* pp0 = Ps + (w * 16 + lr) * PSH + 2 * lc;
        __half* pp1 = pp0 + 8 * PSH;
        #pragma unroll
        for (int nt = 0; nt < 4; nt++) {
            float p00 = __expf(s[nt][0] - m0), p01 = __expf(s[nt][1] - m0);
            float p10 = __expf(s[nt][2] - m1), p11 = __expf(s[nt][3] - m1);
            ls0 += p00 + p01; ls1 += p10 + p11;
            *(__half2*)&pp0[nt * 8] = __floats2half2_rn(p00, p01);
            *(__half2*)&pp1[nt * 8] = __floats2half2_rn(p10, p11);
        }
        ls0 += __shfl_xor_sync(0xffffffff, ls0, 1);
        ls0 += __shfl_xor_sync(0xffffffff, ls0, 2);
        ls1 += __shfl_xor_sync(0xffffffff, ls1, 1);
        ls1 += __shfl_xor_sync(0xffffffff, ls1, 2);
        l0 = l0 * cr0 + ls0;
        l1 = l1 * cr1 + ls1;

        #pragma unroll
        for (int dt = 0; dt < 8; dt++) {
            acc_o[dt][0] *= cr0; acc_o[dt][1] *= cr0;
            acc_o[dt][2] *= cr1; acc_o[dt][3] *= cr1;
        }
        __syncwarp();

        #pragma unroll
        for (int ks = 0; ks < 2; ks++) {
            const __half* pf = Ps + (w * 16 + lr) * PSH + ks * 16 + 2 * lc;
            unsigned a0 = ldu32(pf),     a1 = ldu32(pf + 8 * PSH);
            unsigned a2 = ldu32(pf + 8), a3 = ldu32(pf + 8 * PSH + 8);
            #pragma unroll
            for (int dt = 0; dt < 8; dt++) {
                const __half* vp = vsm + (dt * 8 + lr) * VSH + ks * 16 + 2 * lc;
                mma_f16(acc_o[dt], a0, a1, a2, a3, ldu32(vp), ldu32(vp + 8));
            }
        }
        __syncwarp();
    }

    const float inv0 = 1.f / l0, inv1 = 1.f / l1;
    const int b = bh >> 4, h = bh & 15;
    const int r0 = b * Ss + qb + w * 16 + lr;
    #pragma unroll
    for (int dt = 0; dt < 8; dt++) {
        int col = h * DHd + dt * 8 + 2 * lc;
        *(__half2*)&g_ctxh[(size_t)r0 * Dd + col] =
            __floats2half2_rn(acc_o[dt][0] * inv0, acc_o[dt][1] * inv0);
        *(__half2*)&g_ctxh[(size_t)(r0 + 8) * Dd + col] =
            __floats2half2_rn(acc_o[dt][2] * inv1, acc_o[dt][3] * inv1);
    }
}

// ============ launch ============
extern "C" void kernel_launch(void* const* d_in, const int* in_sizes, int n_in,
                              void* d_out, int out_size)
{
    const float* x  = (const float*)d_in[0];
    const float* Wq = (const float*)d_in[1];
    const float* bq = (const float*)d_in[2];
    const float* Wk = (const float*)d_in[3];
    const float* bk = (const float*)d_in[4];
    const float* Wv = (const float*)d_in[5];
    const float* bv = (const float*)d_in[6];
    const float* Wo = (const float*)d_in[7];
    const float* bo = (const float*)d_in[8];
    float* out = (float*)d_out;

    cudaFuncSetAttribute(qkv_kernel,  cudaFuncAttributeMaxDynamicSharedMemorySize,
                         GEMM_SMEM);
    cudaFuncSetAttribute(oproj_kernel, cudaFuncAttributeMaxDynamicSharedMemorySize,
                         GEMM_SMEM);

    const int total = X4 + 4 * W4;
    cvt_inputs<<<(total + 255) / 256, 256>>>((const float4*)x, (const float4*)Wq,
                                             (const float4*)Wk, (const float4*)Wv,
                                             (const float4*)Wo);

    dim3 gQKV(Dd / 128, Mm / 128, 3);
    qkv_kernel<<<gQKV, 256, GEMM_SMEM>>>(bq, bk, bv);

    dim3 gAtt(Ss / 128, Bb * Hh);
    attn_kernel<<<gAtt, 256>>>();

    dim3 gO(Dd / 128, Mm / 128);
    oproj_kernel<<<gO, 256, GEMM_SMEM>>>(bo, out);
}

// round 16
// speedup vs baseline: 2.2086x; 1.0845x over previous
#include <cuda_runtime.h>
#include <cuda_fp16.h>
#include <cstdint>

#define Bb 4
#define Ss 2048
#define Dd 1024
#define Hh 16
#define DHd 64
#define Mm (Bb*Ss)   // 8192

// Scratch (allocation-free)
__device__ __half g_xh [(size_t)Mm*Dd];
__device__ __half g_wqh[(size_t)Dd*Dd];
__device__ __half g_wkh[(size_t)Dd*Dd];
__device__ __half g_wvh[(size_t)Dd*Dd];
__device__ __half g_woh[(size_t)Dd*Dd];
__device__ __half g_qh [(size_t)Bb*Hh*Ss*DHd];   // q, pre-scaled by 0.125, fp16
__device__ __half g_kh [(size_t)Bb*Hh*Ss*DHd];   // k, fp16
__device__ __half g_vt [(size_t)Bb*Hh*DHd*Ss];   // V TRANSPOSED [b,h,d,s], fp16
__device__ __half g_ctxh[(size_t)Mm*Dd];

__device__ __forceinline__ unsigned ldu32(const __half* p) {
    return *(const unsigned*)p;
}
__device__ __forceinline__ unsigned packh2(float a, float b) {
    __half2 h = __floats2half2_rn(a, b);
    return *(unsigned*)&h;
}

__device__ __forceinline__ void mma_f16(float* c, unsigned a0, unsigned a1,
                                        unsigned a2, unsigned a3,
                                        unsigned b0, unsigned b1) {
    asm volatile(
        "mma.sync.aligned.m16n8k16.row.col.f32.f16.f16.f32 "
        "{%0,%1,%2,%3},{%4,%5,%6,%7},{%8,%9},{%0,%1,%2,%3};"
        : "+f"(c[0]), "+f"(c[1]), "+f"(c[2]), "+f"(c[3])
        : "r"(a0), "r"(a1), "r"(a2), "r"(a3), "r"(b0), "r"(b1));
}

__device__ __forceinline__ void cp16(unsigned dst, const void* src) {
    asm volatile("cp.async.cg.shared.global [%0], [%1], 16;"
                 :: "r"(dst), "l"(src) : "memory");
}
__device__ __forceinline__ void cp_commit() {
    asm volatile("cp.async.commit_group;" ::: "memory");
}
__device__ __forceinline__ void cp_wait1() {
    asm volatile("cp.async.wait_group 1;" ::: "memory");
}

// ============ input conversion: fp32 -> fp16 (direct symbol writes) ============
#define X4 (Mm*Dd/4)
#define W4 (Dd*Dd/4)

__global__ void cvt_inputs(const float4* __restrict__ x,
                           const float4* __restrict__ wq,
                           const float4* __restrict__ wk,
                           const float4* __restrict__ wv,
                           const float4* __restrict__ wo)
{
    int i = blockIdx.x * blockDim.x + threadIdx.x;
    const float4* src; __half2* dst; int j;
    if (i < X4)              { src = x;  dst = (__half2*)g_xh;  j = i; }
    else if (i < X4 + W4)    { src = wq; dst = (__half2*)g_wqh; j = i - X4; }
    else if (i < X4 + 2*W4)  { src = wk; dst = (__half2*)g_wkh; j = i - X4 - W4; }
    else if (i < X4 + 3*W4)  { src = wv; dst = (__half2*)g_wvh; j = i - X4 - 2*W4; }
    else if (i < X4 + 4*W4)  { src = wo; dst = (__half2*)g_woh; j = i - X4 - 3*W4; }
    else return;
    float4 v = src[j];
    dst[2 * j]     = __floats2half2_rn(v.x, v.y);
    dst[2 * j + 1] = __floats2half2_rn(v.z, v.w);
}

// ============ FP16 GEMM core: cp.async 3-stage pipeline, BK=32 (R15-proven) ======
#define SH 40
#define STG (128 * SH)
#define GEMM_SMEM (6 * STG * 2)

__device__ __forceinline__ void gemm_issue(
    const __half* __restrict__ A, const __half* __restrict__ W,
    unsigned as0, unsigned bs0, int s, int bm, int bn, int k0, int tid)
{
    #pragma unroll
    for (int i = 0; i < 2; i++) {
        int idx = tid + i * 256;
        int row = idx >> 2, c8 = (idx & 3) * 8;
        unsigned off = (s * STG + row * SH + c8) * 2;
        cp16(as0 + off, &A[(size_t)(bm + row) * Dd + k0 + c8]);
        cp16(bs0 + off, &W[(size_t)(bn + row) * Dd + k0 + c8]);
    }
}

__device__ __forceinline__ void gemm_core_f16(
    const __half* __restrict__ A, const __half* __restrict__ W,
    __half* As, __half* Bs, int bm, int bn, float acc[4][4][4])
{
    const int tid = threadIdx.x;
    const int lane = tid & 31, wid = tid >> 5;
    const int wm = wid >> 2, wn = wid & 3;
    const int lr = lane >> 2, lc = lane & 3;

    const unsigned as0 = (unsigned)__cvta_generic_to_shared(As);
    const unsigned bs0 = (unsigned)__cvta_generic_to_shared(Bs);

    gemm_issue(A, W, as0, bs0, 0, bm, bn, 0, tid);
    cp_commit();
    gemm_issue(A, W, as0, bs0, 1, bm, bn, 32, tid);
    cp_commit();

    int it = 0;
    for (int k0 = 0; k0 < Dd; k0 += 32, it++) {
        const int buf = it % 3;
        cp_wait1();
        __syncthreads();

        if (k0 + 64 < Dd)
            gemm_issue(A, W, as0, bs0, (it + 2) % 3, bm, bn, k0 + 64, tid);
        cp_commit();

        const __half* as = As + buf * STG;
        const __half* bs = Bs + buf * STG;

        #pragma unroll
        for (int ks = 0; ks < 2; ks++) {
            unsigned af[4][4], bf[4][2];
            #pragma unroll
            for (int mt = 0; mt < 4; mt++) {
                const __half* Ab = as + (wm * 64 + mt * 16 + lr) * SH + ks * 16 + 2 * lc;
                af[mt][0] = ldu32(Ab);
                af[mt][1] = ldu32(Ab + 8 * SH);
                af[mt][2] = ldu32(Ab + 8);
                af[mt][3] = ldu32(Ab + 8 * SH + 8);
            }
            #pragma unroll
            for (int nt = 0; nt < 4; nt++) {
                const __half* Bp = bs + (wn * 32 + nt * 8 + lr) * SH + ks * 16 + 2 * lc;
                bf[nt][0] = ldu32(Bp);
                bf[nt][1] = ldu32(Bp + 8);
            }
            #pragma unroll
            for (int mt = 0; mt < 4; mt++)
                #pragma unroll
                for (int nt = 0; nt < 4; nt++)
                    mma_f16(acc[mt][nt], af[mt][0], af[mt][1], af[mt][2], af[mt][3],
                            bf[nt][0], bf[nt][1]);
        }
    }
}

// ============ QKV projection (q,k -> fp16; v -> fp16 TRANSPOSED) ============
__global__ void __launch_bounds__(256)
qkv_kernel(const float* __restrict__ bq, const float* __restrict__ bk,
           const float* __restrict__ bv)
{
    extern __shared__ __align__(16) __half dsm[];
    __half* As = dsm;
    __half* Bs = dsm + 3 * STG;

    const __half* W; const float* bias; const int which = blockIdx.z;
    if (which == 0)      { W = g_wqh; bias = bq; }
    else if (which == 1) { W = g_wkh; bias = bk; }
    else                 { W = g_wvh; bias = bv; }

    const int bm = blockIdx.y * 128, bn = blockIdx.x * 128;
    float acc[4][4][4] = {};
    gemm_core_f16(g_xh, W, As, Bs, bm, bn, acc);

    const int lane = threadIdx.x & 31, wid = threadIdx.x >> 5;
    const int wm = wid >> 2, wn = wid & 3;
    const int lr = lane >> 2, lc = lane & 3;

    #pragma unroll
    for (int mt = 0; mt < 4; mt++) {
        #pragma unroll
        for (int half_ = 0; half_ < 2; half_++) {
            int m = bm + wm * 64 + mt * 16 + lr + half_ * 8;
            int b = m >> 11, s = m & 2047;
            #pragma unroll
            for (int nt = 0; nt < 4; nt++) {
                int n = bn + wn * 32 + nt * 8 + 2 * lc;
                int h = n >> 6, d = n & 63;
                float vx = acc[mt][nt][half_ * 2 + 0] + bias[n];
                float vy = acc[mt][nt][half_ * 2 + 1] + bias[n + 1];
                if (which == 0) {
                    size_t idx = ((size_t)((b * Hh + h) * Ss + s)) * DHd + d;
                    *(__half2*)&g_qh[idx] = __floats2half2_rn(0.125f * vx, 0.125f * vy);
                } else if (which == 1) {
                    size_t idx = ((size_t)((b * Hh + h) * Ss + s)) * DHd + d;
                    *(__half2*)&g_kh[idx] = __floats2half2_rn(vx, vy);
                } else {
                    size_t base = ((size_t)(b * Hh + h) * DHd + d) * Ss + s;
                    g_vt[base]      = __float2half_rn(vx);
                    g_vt[base + Ss] = __float2half_rn(vy);
                }
            }
        }
    }
}

// ============ Output projection (R15-proven) ============
__global__ void __launch_bounds__(256)
oproj_kernel(const float* __restrict__ bo, float* __restrict__ out)
{
    extern __shared__ __align__(16) __half dsm[];
    __half* As = dsm;
    __half* Bs = dsm + 3 * STG;

    const int bm = blockIdx.y * 128, bn = blockIdx.x * 128;
    float acc[4][4][4] = {};
    gemm_core_f16(g_ctxh, g_woh, As, Bs, bm, bn, acc);

    const int lane = threadIdx.x & 31, wid = threadIdx.x >> 5;
    const int wm = wid >> 2, wn = wid & 3;
    const int lr = lane >> 2, lc = lane & 3;

    #pragma unroll
    for (int mt = 0; mt < 4; mt++) {
        #pragma unroll
        for (int half_ = 0; half_ < 2; half_++) {
            int m = bm + wm * 64 + mt * 16 + lr + half_ * 8;
            #pragma unroll
            for (int nt = 0; nt < 4; nt++) {
                int n = bn + wn * 32 + nt * 8 + 2 * lc;
                float2 v;
                v.x = acc[mt][nt][half_ * 2 + 0] + bo[n];
                v.y = acc[mt][nt][half_ * 2 + 1] + bo[n + 1];
                *(float2*)&out[(size_t)m * Dd + n] = v;
            }
        }
    }
}

// ============ Flash attention: fp16 MMA, cp.async 3-stage K/V, register-P ========
// K tile: 32 tok x 64 halves, stride KSH=72 (144 B rows, 16B-mult ✓, >= 64 ✓).
// V^T tile: 64 dim x 32 halves, stride VSH=40 (80 B rows, 16B-mult ✓, >= 32 ✓).
// P lives in REGISTERS: QK accumulator frags map exactly onto PV A-operand frags.
#define KSH 72
#define VSH 40
#define KBUFH (32 * KSH)   // 2304 halves/stage
#define VBUFH (64 * VSH)   // 2560 halves/stage

__device__ __forceinline__ void attn_issue(
    const __half* __restrict__ Kg, const __half* __restrict__ Vg,
    unsigned ks0, unsigned vs0, int s, int kt, int tid)
{
    int krow = tid >> 3, kc8 = (tid & 7) * 8;
    cp16(ks0 + (s * KBUFH + krow * KSH + kc8) * 2,
         &Kg[(size_t)(kt + krow) * DHd + kc8]);
    int vrow = tid >> 2, vc8 = (tid & 3) * 8;
    cp16(vs0 + (s * VBUFH + vrow * VSH + vc8) * 2,
         &Vg[(size_t)vrow * Ss + kt + vc8]);
}

__global__ void __launch_bounds__(256)
attn_kernel()
{
    __shared__ __align__(16) __half Ks[3 * KBUFH];   // 13.8 KB
    __shared__ __align__(16) __half Vs[3 * VBUFH];   // 15.4 KB

    const int tid = threadIdx.x;
    const int lane = tid & 31, w = tid >> 5;
    const int lr = lane >> 2, lc = lane & 3;
    const int bh = blockIdx.y;
    const int qb = blockIdx.x * 128;

    const __half* Qg = g_qh + ((size_t)bh * Ss + qb) * DHd;
    const __half* Kg = g_kh + (size_t)bh * Ss * DHd;
    const __half* Vg = g_vt + (size_t)bh * DHd * Ss;

    const unsigned ks0 = (unsigned)__cvta_generic_to_shared(Ks);
    const unsigned vs0 = (unsigned)__cvta_generic_to_shared(Vs);

    // prologue: stages 0 and 1
    attn_issue(Kg, Vg, ks0, vs0, 0, 0, tid);
    cp_commit();
    attn_issue(Kg, Vg, ks0, vs0, 1, 32, tid);
    cp_commit();

    // Q frags direct from gmem (fp16, pre-scaled by 0.125) — overlaps copies
    unsigned qf[4][4];
    {
        const __half* q0 = Qg + (w * 16 + lr) * DHd;
        #pragma unroll
        for (int ks = 0; ks < 4; ks++) {
            qf[ks][0] = ldu32(q0 + ks * 16 + 2 * lc);
            qf[ks][1] = ldu32(q0 + 8 * DHd + ks * 16 + 2 * lc);
            qf[ks][2] = ldu32(q0 + ks * 16 + 2 * lc + 8);
            qf[ks][3] = ldu32(q0 + 8 * DHd + ks * 16 + 2 * lc + 8);
        }
    }

    float acc_o[8][4] = {};
    float m0 = -1e30f, m1 = -1e30f, l0 = 0.f, l1 = 0.f;

    int it = 0;
    for (int kt = 0; kt < Ss; kt += 32, it++) {
        const int buf = it % 3;
        cp_wait1();
        __syncthreads();

        if (kt + 64 < Ss)
            attn_issue(Kg, Vg, ks0, vs0, (it + 2) % 3, kt + 64, tid);
        cp_commit();

        const __half* ksm = Ks + buf * KBUFH;
        const __half* vsm = Vs + buf * VBUFH;

        // S = (Q/8) K^T   (fp16 MMA, 4 ksteps of 16)
        float s[4][4] = {};
        #pragma unroll
        for (int ks = 0; ks < 4; ks++) {
            #pragma unroll
            for (int nt = 0; nt < 4; nt++) {
                const __half* kp = ksm + (nt * 8 + lr) * KSH + ks * 16 + 2 * lc;
                mma_f16(s[nt], qf[ks][0], qf[ks][1], qf[ks][2], qf[ks][3],
                        ldu32(kp), ldu32(kp + 8));
            }
        }

        // online softmax (rows lr, lr+8)
        float mx0 = -1e30f, mx1 = -1e30f;
        #pragma unroll
        for (int nt = 0; nt < 4; nt++) {
            mx0 = fmaxf(mx0, fmaxf(s[nt][0], s[nt][1]));
            mx1 = fmaxf(mx1, fmaxf(s[nt][2], s[nt][3]));
        }
        mx0 = fmaxf(mx0, __shfl_xor_sync(0xffffffff, mx0, 1));
        mx0 = fmaxf(mx0, __shfl_xor_sync(0xffffffff, mx0, 2));
        mx1 = fmaxf(mx1, __shfl_xor_sync(0xffffffff, mx1, 1));
        mx1 = fmaxf(mx1, __shfl_xor_sync(0xffffffff, mx1, 2));

        float mn0 = fmaxf(m0, mx0), mn1 = fmaxf(m1, mx1);
        float cr0 = __expf(m0 - mn0), cr1 = __expf(m1 - mn1);
        m0 = mn0; m1 = mn1;

        // exp + pack P directly into A-operand frags (no smem round-trip):
        // pa[ks][0]=rows lr cols(2lc,2lc+1) of nt=2ks ; [1]=rows lr+8 same;
        // [2],[3] = nt=2ks+1 (cols +8).
        unsigned pa[2][4];
        float ls0 = 0.f, ls1 = 0.f;
        #pragma unroll
        for (int nt = 0; nt < 4; nt++) {
            float p00 = __expf(s[nt][0] - m0), p01 = __expf(s[nt][1] - m0);
            float p10 = __expf(s[nt][2] - m1), p11 = __expf(s[nt][3] - m1);
            ls0 += p00 + p01; ls1 += p10 + p11;
            const int ks = nt >> 1, hi = (nt & 1) * 2;
            pa[ks][hi + 0] = packh2(p00, p01);
            pa[ks][hi + 1] = packh2(p10, p11);
        }
        ls0 += __shfl_xor_sync(0xffffffff, ls0, 1);
        ls0 += __shfl_xor_sync(0xffffffff, ls0, 2);
        ls1 += __shfl_xor_sync(0xffffffff, ls1, 1);
        ls1 += __shfl_xor_sync(0xffffffff, ls1, 2);
        l0 = l0 * cr0 + ls0;
        l1 = l1 * cr1 + ls1;

        #pragma unroll
        for (int dt = 0; dt < 8; dt++) {
            acc_o[dt][0] *= cr0; acc_o[dt][1] *= cr0;
            acc_o[dt][2] *= cr1; acc_o[dt][3] *= cr1;
        }

        // O += P V   (fp16 MMA, A-frags from registers; B from V^T smem)
        #pragma unroll
        for (int ks = 0; ks < 2; ks++) {
            #pragma unroll
            for (int dt = 0; dt < 8; dt++) {
                const __half* vp = vsm + (dt * 8 + lr) * VSH + ks * 16 + 2 * lc;
                mma_f16(acc_o[dt], pa[ks][0], pa[ks][1], pa[ks][2], pa[ks][3],
                        ldu32(vp), ldu32(vp + 8));
            }
        }
    }

    const float inv0 = 1.f / l0, inv1 = 1.f / l1;
    const int b = bh >> 4, h = bh & 15;
    const int r0 = b * Ss + qb + w * 16 + lr;
    #pragma unroll
    for (int dt = 0; dt < 8; dt++) {
        int col = h * DHd + dt * 8 + 2 * lc;
        *(__half2*)&g_ctxh[(size_t)r0 * Dd + col] =
            __floats2half2_rn(acc_o[dt][0] * inv0, acc_o[dt][1] * inv0);
        *(__half2*)&g_ctxh[(size_t)(r0 + 8) * Dd + col] =
            __floats2half2_rn(acc_o[dt][2] * inv1, acc_o[dt][3] * inv1);
    }
}

// ============ launch ============
extern "C" void kernel_launch(void* const* d_in, const int* in_sizes, int n_in,
                              void* d_out, int out_size)
{
    const float* x  = (const float*)d_in[0];
    const float* Wq = (const float*)d_in[1];
    const float* bq = (const float*)d_in[2];
    const float* Wk = (const float*)d_in[3];
    const float* bk = (const float*)d_in[4];
    const float* Wv = (const float*)d_in[5];
    const float* bv = (const float*)d_in[6];
    const float* Wo = (const float*)d_in[7];
    const float* bo = (const float*)d_in[8];
    float* out = (float*)d_out;

    cudaFuncSetAttribute(qkv_kernel,  cudaFuncAttributeMaxDynamicSharedMemorySize,
                         GEMM_SMEM);
    cudaFuncSetAttribute(oproj_kernel, cudaFuncAttributeMaxDynamicSharedMemorySize,
                         GEMM_SMEM);

    const int total = X4 + 4 * W4;
    cvt_inputs<<<(total + 255) / 256, 256>>>((const float4*)x, (const float4*)Wq,
                                             (const float4*)Wk, (const float4*)Wv,
                                             (const float4*)Wo);

    dim3 gQKV(Dd / 128, Mm / 128, 3);
    qkv_kernel<<<gQKV, 256, GEMM_SMEM>>>(bq, bk, bv);

    dim3 gAtt(Ss / 128, Bb * Hh);
    attn_kernel<<<gAtt, 256>>>();

    dim3 gO(Dd / 128, Mm / 128);
    oproj_kernel<<<gO, 256, GEMM_SMEM>>>(bo, out);
}

// round 17
// speedup vs baseline: 2.3013x; 1.0420x over previous
#include <cuda_runtime.h>
#include <cuda_fp16.h>
#include <cstdint>

#define Bb 4
#define Ss 2048
#define Dd 1024
#define Hh 16
#define DHd 64
#define Mm (Bb*Ss)   // 8192

// Scratch (allocation-free)
__device__ __half g_xh [(size_t)Mm*Dd];
__device__ __half g_wqh[(size_t)Dd*Dd];
__device__ __half g_wkh[(size_t)Dd*Dd];
__device__ __half g_wvh[(size_t)Dd*Dd];
__device__ __half g_woh[(size_t)Dd*Dd];
__device__ __half g_qh [(size_t)Bb*Hh*Ss*DHd];   // q, pre-scaled by 0.125, fp16
__device__ __half g_kh [(size_t)Bb*Hh*Ss*DHd];   // k, fp16
__device__ __half g_vt [(size_t)Bb*Hh*DHd*Ss];   // V TRANSPOSED [b,h,d,s], fp16
__device__ __half g_ctxh[(size_t)Mm*Dd];

__device__ __forceinline__ unsigned ldu32(const __half* p) {
    return *(const unsigned*)p;
}
__device__ __forceinline__ unsigned packh2(float a, float b) {
    __half2 h = __floats2half2_rn(a, b);
    return *(unsigned*)&h;
}

__device__ __forceinline__ void mma_f16(float* c, unsigned a0, unsigned a1,
                                        unsigned a2, unsigned a3,
                                        unsigned b0, unsigned b1) {
    asm volatile(
        "mma.sync.aligned.m16n8k16.row.col.f32.f16.f16.f32 "
        "{%0,%1,%2,%3},{%4,%5,%6,%7},{%8,%9},{%0,%1,%2,%3};"
        : "+f"(c[0]), "+f"(c[1]), "+f"(c[2]), "+f"(c[3])
        : "r"(a0), "r"(a1), "r"(a2), "r"(a3), "r"(b0), "r"(b1));
}

__device__ __forceinline__ void ldsm4(unsigned& r0, unsigned& r1,
                                      unsigned& r2, unsigned& r3, unsigned addr) {
    asm volatile("ldmatrix.sync.aligned.m8n8.x4.shared.b16 {%0,%1,%2,%3}, [%4];"
                 : "=r"(r0), "=r"(r1), "=r"(r2), "=r"(r3) : "r"(addr));
}

__device__ __forceinline__ void cp16(unsigned dst, const void* src) {
    asm volatile("cp.async.cg.shared.global [%0], [%1], 16;"
                 :: "r"(dst), "l"(src) : "memory");
}
__device__ __forceinline__ void cp_commit() {
    asm volatile("cp.async.commit_group;" ::: "memory");
}
__device__ __forceinline__ void cp_wait1() {
    asm volatile("cp.async.wait_group 1;" ::: "memory");
}

// ============ input conversion: fp32 -> fp16 (direct symbol writes) ============
#define X4 (Mm*Dd/4)
#define W4 (Dd*Dd/4)

__global__ void cvt_inputs(const float4* __restrict__ x,
                           const float4* __restrict__ wq,
                           const float4* __restrict__ wk,
                           const float4* __restrict__ wv,
                           const float4* __restrict__ wo)
{
    int i = blockIdx.x * blockDim.x + threadIdx.x;
    const float4* src; __half2* dst; int j;
    if (i < X4)              { src = x;  dst = (__half2*)g_xh;  j = i; }
    else if (i < X4 + W4)    { src = wq; dst = (__half2*)g_wqh; j = i - X4; }
    else if (i < X4 + 2*W4)  { src = wk; dst = (__half2*)g_wkh; j = i - X4 - W4; }
    else if (i < X4 + 3*W4)  { src = wv; dst = (__half2*)g_wvh; j = i - X4 - 2*W4; }
    else if (i < X4 + 4*W4)  { src = wo; dst = (__half2*)g_woh; j = i - X4 - 3*W4; }
    else return;
    float4 v = src[j];
    dst[2 * j]     = __floats2half2_rn(v.x, v.y);
    dst[2 * j + 1] = __floats2half2_rn(v.z, v.w);
}

// ============ FP16 GEMM core: cp.async 3-stage + ldmatrix frag loads ============
// Layout identical to R15/R16 (SH=40); ldmatrix loads the SAME values into the
// SAME registers -> bit-identical math. 12 ldmatrix/iter replace 48 LDS.32.
#define SH 40
#define STG (128 * SH)
#define GEMM_SMEM (6 * STG * 2)

__device__ __forceinline__ void gemm_issue(
    const __half* __restrict__ A, const __half* __restrict__ W,
    unsigned as0, unsigned bs0, int s, int bm, int bn, int k0, int tid)
{
    #pragma unroll
    for (int i = 0; i < 2; i++) {
        int idx = tid + i * 256;
        int row = idx >> 2, c8 = (idx & 3) * 8;
        unsigned off = (s * STG + row * SH + c8) * 2;
        cp16(as0 + off, &A[(size_t)(bm + row) * Dd + k0 + c8]);
        cp16(bs0 + off, &W[(size_t)(bn + row) * Dd + k0 + c8]);
    }
}

__device__ __forceinline__ void gemm_core_f16(
    const __half* __restrict__ A, const __half* __restrict__ W,
    __half* As, __half* Bs, int bm, int bn, float acc[4][4][4])
{
    const int tid = threadIdx.x;
    const int lane = tid & 31, wid = tid >> 5;
    const int wm = wid >> 2, wn = wid & 3;

    const unsigned as0 = (unsigned)__cvta_generic_to_shared(As);
    const unsigned bs0 = (unsigned)__cvta_generic_to_shared(Bs);

    // ldmatrix lane-address offsets (bytes, within a stage)
    // A 16x16 tile (per mt): lanes 0-15 -> rows, lanes 16-31 -> col-half +8
    const unsigned a_lm = ((wm * 64 + (lane & 15)) * SH + (lane >> 4) * 8) * 2;
    // B nt-pair tile: lanes 0-15 -> nt0 (rows x col-halves), 16-31 -> nt1
    const unsigned b_lm = ((wn * 32 + (lane >> 4) * 8 + (lane & 7)) * SH
                           + ((lane >> 3) & 1) * 8) * 2;

    gemm_issue(A, W, as0, bs0, 0, bm, bn, 0, tid);
    cp_commit();
    gemm_issue(A, W, as0, bs0, 1, bm, bn, 32, tid);
    cp_commit();

    int it = 0;
    for (int k0 = 0; k0 < Dd; k0 += 32, it++) {
        const int buf = it % 3;
        cp_wait1();
        __syncthreads();

        if (k0 + 64 < Dd)
            gemm_issue(A, W, as0, bs0, (it + 2) % 3, bm, bn, k0 + 64, tid);
        cp_commit();

        const unsigned as_b = as0 + buf * STG * 2;
        const unsigned bs_b = bs0 + buf * STG * 2;

        #pragma unroll
        for (int ks = 0; ks < 2; ks++) {
            unsigned af[4][4], bf[4][2];
            #pragma unroll
            for (int mt = 0; mt < 4; mt++)
                ldsm4(af[mt][0], af[mt][1], af[mt][2], af[mt][3],
                      as_b + a_lm + mt * 16 * SH * 2 + ks * 32);
            #pragma unroll
            for (int np = 0; np < 2; np++)
                ldsm4(bf[2 * np][0], bf[2 * np][1], bf[2 * np + 1][0], bf[2 * np + 1][1],
                      bs_b + b_lm + np * 16 * SH * 2 + ks * 32);
            #pragma unroll
            for (int mt = 0; mt < 4; mt++)
                #pragma unroll
                for (int nt = 0; nt < 4; nt++)
                    mma_f16(acc[mt][nt], af[mt][0], af[mt][1], af[mt][2], af[mt][3],
                            bf[nt][0], bf[nt][1]);
        }
    }
}

// ============ QKV projection (q,k -> fp16; v -> fp16 TRANSPOSED) ============
__global__ void __launch_bounds__(256)
qkv_kernel(const float* __restrict__ bq, const float* __restrict__ bk,
           const float* __restrict__ bv)
{
    extern __shared__ __align__(16) __half dsm[];
    __half* As = dsm;
    __half* Bs = dsm + 3 * STG;

    const __half* W; const float* bias; const int which = blockIdx.z;
    if (which == 0)      { W = g_wqh; bias = bq; }
    else if (which == 1) { W = g_wkh; bias = bk; }
    else                 { W = g_wvh; bias = bv; }

    const int bm = blockIdx.y * 128, bn = blockIdx.x * 128;
    float acc[4][4][4] = {};
    gemm_core_f16(g_xh, W, As, Bs, bm, bn, acc);

    const int lane = threadIdx.x & 31, wid = threadIdx.x >> 5;
    const int wm = wid >> 2, wn = wid & 3;
    const int lr = lane >> 2, lc = lane & 3;

    #pragma unroll
    for (int mt = 0; mt < 4; mt++) {
        #pragma unroll
        for (int half_ = 0; half_ < 2; half_++) {
            int m = bm + wm * 64 + mt * 16 + lr + half_ * 8;
            int b = m >> 11, s = m & 2047;
            #pragma unroll
            for (int nt = 0; nt < 4; nt++) {
                int n = bn + wn * 32 + nt * 8 + 2 * lc;
                int h = n >> 6, d = n & 63;
                float vx = acc[mt][nt][half_ * 2 + 0] + bias[n];
                float vy = acc[mt][nt][half_ * 2 + 1] + bias[n + 1];
                if (which == 0) {
                    size_t idx = ((size_t)((b * Hh + h) * Ss + s)) * DHd + d;
                    *(__half2*)&g_qh[idx] = __floats2half2_rn(0.125f * vx, 0.125f * vy);
                } else if (which == 1) {
                    size_t idx = ((size_t)((b * Hh + h) * Ss + s)) * DHd + d;
                    *(__half2*)&g_kh[idx] = __floats2half2_rn(vx, vy);
                } else {
                    size_t base = ((size_t)(b * Hh + h) * DHd + d) * Ss + s;
                    g_vt[base]      = __float2half_rn(vx);
                    g_vt[base + Ss] = __float2half_rn(vy);
                }
            }
        }
    }
}

// ============ Output projection ============
__global__ void __launch_bounds__(256)
oproj_kernel(const float* __restrict__ bo, float* __restrict__ out)
{
    extern __shared__ __align__(16) __half dsm[];
    __half* As = dsm;
    __half* Bs = dsm + 3 * STG;

    const int bm = blockIdx.y * 128, bn = blockIdx.x * 128;
    float acc[4][4][4] = {};
    gemm_core_f16(g_ctxh, g_woh, As, Bs, bm, bn, acc);

    const int lane = threadIdx.x & 31, wid = threadIdx.x >> 5;
    const int wm = wid >> 2, wn = wid & 3;
    const int lr = lane >> 2, lc = lane & 3;

    #pragma unroll
    for (int mt = 0; mt < 4; mt++) {
        #pragma unroll
        for (int half_ = 0; half_ < 2; half_++) {
            int m = bm + wm * 64 + mt * 16 + lr + half_ * 8;
            #pragma unroll
            for (int nt = 0; nt < 4; nt++) {
                int n = bn + wn * 32 + nt * 8 + 2 * lc;
                float2 v;
                v.x = acc[mt][nt][half_ * 2 + 0] + bo[n];
                v.y = acc[mt][nt][half_ * 2 + 1] + bo[n + 1];
                *(float2*)&out[(size_t)m * Dd + n] = v;
            }
        }
    }
}

// ============ Flash attention: R16 verbatim (fp16 MMA, cp.async, register-P) ====
#define KSH 72
#define VSH 40
#define KBUFH (32 * KSH)
#define VBUFH (64 * VSH)

__device__ __forceinline__ void attn_issue(
    const __half* __restrict__ Kg, const __half* __restrict__ Vg,
    unsigned ks0, unsigned vs0, int s, int kt, int tid)
{
    int krow = tid >> 3, kc8 = (tid & 7) * 8;
    cp16(ks0 + (s * KBUFH + krow * KSH + kc8) * 2,
         &Kg[(size_t)(kt + krow) * DHd + kc8]);
    int vrow = tid >> 2, vc8 = (tid & 3) * 8;
    cp16(vs0 + (s * VBUFH + vrow * VSH + vc8) * 2,
         &Vg[(size_t)vrow * Ss + kt + vc8]);
}

__global__ void __launch_bounds__(256)
attn_kernel()
{
    __shared__ __align__(16) __half Ks[3 * KBUFH];
    __shared__ __align__(16) __half Vs[3 * VBUFH];

    const int tid = threadIdx.x;
    const int lane = tid & 31, w = tid >> 5;
    const int lr = lane >> 2, lc = lane & 3;
    const int bh = blockIdx.y;
    const int qb = blockIdx.x * 128;

    const __half* Qg = g_qh + ((size_t)bh * Ss + qb) * DHd;
    const __half* Kg = g_kh + (size_t)bh * Ss * DHd;
    const __half* Vg = g_vt + (size_t)bh * DHd * Ss;

    const unsigned ks0 = (unsigned)__cvta_generic_to_shared(Ks);
    const unsigned vs0 = (unsigned)__cvta_generic_to_shared(Vs);

    attn_issue(Kg, Vg, ks0, vs0, 0, 0, tid);
    cp_commit();
    attn_issue(Kg, Vg, ks0, vs0, 1, 32, tid);
    cp_commit();

    unsigned qf[4][4];
    {
        const __half* q0 = Qg + (w * 16 + lr) * DHd;
        #pragma unroll
        for (int ks = 0; ks < 4; ks++) {
            qf[ks][0] = ldu32(q0 + ks * 16 + 2 * lc);
            qf[ks][1] = ldu32(q0 + 8 * DHd + ks * 16 + 2 * lc);
            qf[ks][2] = ldu32(q0 + ks * 16 + 2 * lc + 8);
            qf[ks][3] = ldu32(q0 + 8 * DHd + ks * 16 + 2 * lc + 8);
        }
    }

    float acc_o[8][4] = {};
    float m0 = -1e30f, m1 = -1e30f, l0 = 0.f, l1 = 0.f;

    int it = 0;
    for (int kt = 0; kt < Ss; kt += 32, it++) {
        const int buf = it % 3;
        cp_wait1();
        __syncthreads();

        if (kt + 64 < Ss)
            attn_issue(Kg, Vg, ks0, vs0, (it + 2) % 3, kt + 64, tid);
        cp_commit();

        const __half* ksm = Ks + buf * KBUFH;
        const __half* vsm = Vs + buf * VBUFH;

        float s[4][4] = {};
        #pragma unroll
        for (int ks = 0; ks < 4; ks++) {
            #pragma unroll
            for (int nt = 0; nt < 4; nt++) {
                const __half* kp = ksm + (nt * 8 + lr) * KSH + ks * 16 + 2 * lc;
                mma_f16(s[nt], qf[ks][0], qf[ks][1], qf[ks][2], qf[ks][3],
                        ldu32(kp), ldu32(kp + 8));
            }
        }

        float mx0 = -1e30f, mx1 = -1e30f;
        #pragma unroll
        for (int nt = 0; nt < 4; nt++) {
            mx0 = fmaxf(mx0, fmaxf(s[nt][0], s[nt][1]));
            mx1 = fmaxf(mx1, fmaxf(s[nt][2], s[nt][3]));
        }
        mx0 = fmaxf(mx0, __shfl_xor_sync(0xffffffff, mx0, 1));
        mx0 = fmaxf(mx0, __shfl_xor_sync(0xffffffff, mx0, 2));
        mx1 = fmaxf(mx1, __shfl_xor_sync(0xffffffff, mx1, 1));
        mx1 = fmaxf(mx1, __shfl_xor_sync(0xffffffff, mx1, 2));

        float mn0 = fmaxf(m0, mx0), mn1 = fmaxf(m1, mx1);
        float cr0 = __expf(m0 - mn0), cr1 = __expf(m1 - mn1);
        m0 = mn0; m1 = mn1;

        unsigned pa[2][4];
        float ls0 = 0.f, ls1 = 0.f;
        #pragma unroll
        for (int nt = 0; nt < 4; nt++) {
            float p00 = __expf(s[nt][0] - m0), p01 = __expf(s[nt][1] - m0);
            float p10 = __expf(s[nt][2] - m1), p11 = __expf(s[nt][3] - m1);
            ls0 += p00 + p01; ls1 += p10 + p11;
            const int ks = nt >> 1, hi = (nt & 1) * 2;
            pa[ks][hi + 0] = packh2(p00, p01);
            pa[ks][hi + 1] = packh2(p10, p11);
        }
        ls0 += __shfl_xor_sync(0xffffffff, ls0, 1);
        ls0 += __shfl_xor_sync(0xffffffff, ls0, 2);
        ls1 += __shfl_xor_sync(0xffffffff, ls1, 1);
        ls1 += __shfl_xor_sync(0xffffffff, ls1, 2);
        l0 = l0 * cr0 + ls0;
        l1 = l1 * cr1 + ls1;

        #pragma unroll
        for (int dt = 0; dt < 8; dt++) {
            acc_o[dt][0] *= cr0; acc_o[dt][1] *= cr0;
            acc_o[dt][2] *= cr1; acc_o[dt][3] *= cr1;
        }

        #pragma unroll
        for (int ks = 0; ks < 2; ks++) {
            #pragma unroll
            for (int dt = 0; dt < 8; dt++) {
                const __half* vp = vsm + (dt * 8 + lr) * VSH + ks * 16 + 2 * lc;
                mma_f16(acc_o[dt], pa[ks][0], pa[ks][1], pa[ks][2], pa[ks][3],
                        ldu32(vp), ldu32(vp + 8));
            }
        }
    }

    const float inv0 = 1.f / l0, inv1 = 1.f / l1;
    const int b = bh >> 4, h = bh & 15;
    const int r0 = b * Ss + qb + w * 16 + lr;
    #pragma unroll
    for (int dt = 0; dt < 8; dt++) {
        int col = h * DHd + dt * 8 + 2 * lc;
        *(__half2*)&g_ctxh[(size_t)r0 * Dd + col] =
            __floats2half2_rn(acc_o[dt][0] * inv0, acc_o[dt][1] * inv0);
        *(__half2*)&g_ctxh[(size_t)(r0 + 8) * Dd + col] =
            __floats2half2_rn(acc_o[dt][2] * inv1, acc_o[dt][3] * inv1);
    }
}

// ============ launch ============
extern "C" void kernel_launch(void* const* d_in, const int* in_sizes, int n_in,
                              void* d_out, int out_size)
{
    const float* x  = (const float*)d_in[0];
    const float* Wq = (const float*)d_in[1];
    const float* bq = (const float*)d_in[2];
    const float* Wk = (const float*)d_in[3];
    const float* bk = (const float*)d_in[4];
    const float* Wv = (const float*)d_in[5];
    const float* bv = (const float*)d_in[6];
    const float* Wo = (const float*)d_in[7];
    const float* bo = (const float*)d_in[8];
    float* out = (float*)d_out;

    cudaFuncSetAttribute(qkv_kernel,  cudaFuncAttributeMaxDynamicSharedMemorySize,
                         GEMM_SMEM);
    cudaFuncSetAttribute(oproj_kernel, cudaFuncAttributeMaxDynamicSharedMemorySize,
                         GEMM_SMEM);

    const int total = X4 + 4 * W4;
    cvt_inputs<<<(total + 255) / 256, 256>>>((const float4*)x, (const float4*)Wq,
                                             (const float4*)Wk, (const float4*)Wv,
                                             (const float4*)Wo);

    dim3 gQKV(Dd / 128, Mm / 128, 3);
    qkv_kernel<<<gQKV, 256, GEMM_SMEM>>>(bq, bk, bv);

    dim3 gAtt(Ss / 128, Bb * Hh);
    attn_kernel<<<gAtt, 256>>>();

    dim3 gO(Dd / 128, Mm / 128);
    oproj_kernel<<<gO, 256, GEMM_SMEM>>>(bo, out);
}